// round 3
// baseline (speedup 1.0000x reference)
#include <cuda_runtime.h>

// ---------------------------------------------------------------------------
// Conv_2259152798130 — fused e3nn edge conv, tf32 mma + cp.async pipeline.
//   h = relu(edge_attr @ W1 + b1)          [E,64]
//   w = h @ W2 + b2                        [E,2304]  (tf32 mma, never stored)
//   region-aware contraction -> msg[E,80] -> atomic segment sum
//   out = residual + segment_mean   (final_kernel also re-zeroes scratch)
// ---------------------------------------------------------------------------

#define NN       10000
#define OUT_DIM  80
#define NORM_V        0.14433756729740643f   // 1/sqrt(48)
#define INV_SQRT3_V   0.57735026918962576f
#define RSQRT32_V     0.17677669529663687f   // 1/sqrt(32)

// zero-initialized at module load; final_kernel restores zeros each run
__device__ float g_sums[NN * OUT_DIM];
__device__ float g_cnt[NN];

__device__ __forceinline__ float ftf32(float x) {
    float r;
    asm("cvt.rna.tf32.f32 %0, %1;" : "=f"(r) : "f"(x));
    return r;
}

__device__ __forceinline__ void mma_tf32(float c[4], const unsigned a[4],
                                         unsigned b0, unsigned b1) {
    asm volatile(
        "mma.sync.aligned.m16n8k8.row.col.f32.tf32.tf32.f32 "
        "{%0,%1,%2,%3}, {%4,%5,%6,%7}, {%8,%9}, {%0,%1,%2,%3};"
        : "+f"(c[0]), "+f"(c[1]), "+f"(c[2]), "+f"(c[3])
        : "r"(a[0]), "r"(a[1]), "r"(a[2]), "r"(a[3]), "r"(b0), "r"(b1));
}

__device__ __forceinline__ void cp_commit() {
    asm volatile("cp.async.commit_group;" ::: "memory");
}
template <int N>
__device__ __forceinline__ void cp_wait() {
    asm volatile("cp.async.wait_group %0;" :: "n"(N) : "memory");
}

// prefetch one 64x64 W2 chunk (raw fp32, XOR-swizzled) via cp.async 16B
__device__ __forceinline__ void prefetch_chunk(
    float* buf, const float* __restrict__ w2, int j0, int tid)
{
#pragma unroll
    for (int t = 0; t < 2; t++) {
        const int i = tid + t * 512;      // 0..1023 over 1024 float4
        const int k = i >> 4;             // k row 0..63
        const int c = (i & 15) << 2;      // col 0,4,..,60
        unsigned dst = (unsigned)__cvta_generic_to_shared(
            buf + k * 64 + (c ^ ((k & 3) << 3)));
        const float* src = w2 + k * 2304 + j0 + c;
        asm volatile("cp.async.cg.shared.global [%0], [%1], 16;"
                     :: "r"(dst), "l"(src));
    }
}

// ---------------------------------------------------------------------------
// Shared layout (floats), 256 edges/block, total 57600 floats = 230400 B
//   H_s   [256][64]   @ 0       (h, tf32-rounded)
//   Wst   [3][64][64] @ 16384   (cp.async stages; W1 aliased here in phase 0)
//   b2a   [2304]      @ 28672
//   x0_s  [256][33]   @ 30976
//   y1_s  [256][17]   @ 39424
//   z1_s  [256][49]   @ 43776
//   sh0_s [256]       @ 56320
//   sh1_s [256][3]    @ 56576
//   dst_s [256] int   @ 57344
// ---------------------------------------------------------------------------
#define SMEM_BYTES (57600 * 4)

__global__ __launch_bounds__(512, 1) void edge_kernel(
    int E,
    const int*   __restrict__ dst,
    const float* __restrict__ x_src,
    const float* __restrict__ sh,
    const float* __restrict__ edge_attr,
    const float* __restrict__ w1,
    const float* __restrict__ b1,
    const float* __restrict__ w2,
    const float* __restrict__ b2)
{
    extern __shared__ float smem[];
    float* H_s   = smem;
    float* Wst   = smem + 16384;
    float* b2a   = smem + 28672;
    float* x0_s  = smem + 30976;
    float* y1_s  = smem + 39424;
    float* z1_s  = smem + 43776;
    float* sh0_s = smem + 56320;
    float* sh1_s = smem + 56576;
    int*   dst_s = (int*)(smem + 57344);
    float* W1_s  = Wst;                    // phase-0 alias (2048 <= 12288)

    const int tid   = threadIdx.x;
    const int eBase = blockIdx.x * 256;
    const int e     = tid & 255;
    const int half  = tid >> 8;
    const int ge    = eBase + e;
    const bool valid = (ge < E);

    // ---- Phase 0: stage W1/b2, per-edge features ----
    ((float4*)W1_s)[tid] = ((const float4*)w1)[tid];      // 512 float4 = 2048 f
    for (int i = tid; i < 576; i += 512)
        ((float4*)b2a)[i] = ((const float4*)b2)[i];       // full b2 (2304 f)

    if (half == 0) {   // one thread per edge
        dst_s[e] = valid ? dst[ge] : 0;
        float s0 = 0.f, s1 = 0.f, s2 = 0.f, s3 = 0.f;
        if (valid) {
            const float4 shv = *(const float4*)&sh[ge * 4];
            s0 = shv.x; s1 = shv.y; s2 = shv.z; s3 = shv.w;
        }
        sh0_s[e] = s0;
        sh1_s[e * 3 + 0] = s1; sh1_s[e * 3 + 1] = s2; sh1_s[e * 3 + 2] = s3;
#pragma unroll
        for (int q = 0; q < 8; q++) {
            float4 v = valid ? ((const float4*)&x_src[ge * 80])[q]
                             : make_float4(0.f, 0.f, 0.f, 0.f);
            x0_s[e * 33 + q * 4 + 0] = v.x;
            x0_s[e * 33 + q * 4 + 1] = v.y;
            x0_s[e * 33 + q * 4 + 2] = v.z;
            x0_s[e * 33 + q * 4 + 3] = v.w;
        }
#pragma unroll
        for (int u = 0; u < 16; u++) {
            float a = 0.f, b = 0.f, c = 0.f;
            if (valid) {
                a = x_src[ge * 80 + 32 + u * 3 + 0];
                b = x_src[ge * 80 + 32 + u * 3 + 1];
                c = x_src[ge * 80 + 32 + u * 3 + 2];
            }
            y1_s[e * 17 + u] = INV_SQRT3_V * (a * s1 + b * s2 + c * s3);
            z1_s[e * 49 + u * 3 + 0] = a * s0;
            z1_s[e * 49 + u * 3 + 1] = b * s0;
            z1_s[e * 49 + u * 3 + 2] = c * s0;
        }
    }

    float attr[32];
#pragma unroll
    for (int q = 0; q < 8; q++) {
        float4 v = valid ? ((const float4*)&edge_attr[ge * 32])[q]
                         : make_float4(0.f, 0.f, 0.f, 0.f);
        attr[q * 4 + 0] = v.x; attr[q * 4 + 1] = v.y;
        attr[q * 4 + 2] = v.z; attr[q * 4 + 3] = v.w;
    }
    __syncthreads();

    // layer-1 MLP: each half computes 32 of the 64 h outputs of edge e
#pragma unroll 2
    for (int jj = 0; jj < 32; jj++) {
        const int j = half * 32 + jj;
        float acc = __ldg(&b1[j]);
#pragma unroll
        for (int i = 0; i < 32; i++)
            acc = fmaf(attr[i], W1_s[i * 64 + j], acc);
        H_s[e * 64 + j] = ftf32(fmaxf(acc, 0.0f));
    }
    __syncthreads();

    // ---- kick off cp.async pipeline (overwrites W1 alias; H is done) ----
    prefetch_chunk(Wst,        w2, 0,  tid); cp_commit();
    prefetch_chunk(Wst + 4096, w2, 64, tid); cp_commit();

    // ---- A fragments (chunk-invariant) ----
    const int lane = tid & 31;
    const int warp = tid >> 5;          // 0..15 -> edges warp*16 .. +15
    const int gid  = lane >> 2;
    const int qd   = lane & 3;
    const int er0  = warp * 16 + gid;
    const int er1  = er0 + 8;

    unsigned a[8][4];
#pragma unroll
    for (int ks = 0; ks < 8; ks++) {
        a[ks][0] = __float_as_uint(H_s[er0 * 64 + ks * 8 + qd]);
        a[ks][1] = __float_as_uint(H_s[er1 * 64 + ks * 8 + qd]);
        a[ks][2] = __float_as_uint(H_s[er0 * 64 + ks * 8 + qd + 4]);
        a[ks][3] = __float_as_uint(H_s[er1 * 64 + ks * 8 + qd + 4]);
    }

    // accumulators
    float acc0[2][4][2];
    float cacc[2][2][2];
    float dacc[2][2][2][3];
#pragma unroll
    for (int r = 0; r < 2; r++) {
#pragma unroll
        for (int n = 0; n < 4; n++) { acc0[r][n][0] = 0.f; acc0[r][n][1] = 0.f; }
#pragma unroll
        for (int p = 0; p < 2; p++) {
            cacc[r][p][0] = 0.f; cacc[r][p][1] = 0.f;
#pragma unroll
            for (int j = 0; j < 2; j++) {
                dacc[r][p][j][0] = 0.f; dacc[r][p][j][1] = 0.f; dacc[r][p][j][2] = 0.f;
            }
        }
    }

    // ---- main pipelined loop over 36 column chunks ----
#pragma unroll 1
    for (int ch = 0; ch < 36; ch++) {
        cp_wait<1>();          // group(ch) complete (own thread)
        __syncthreads();       // all threads' data visible; chunk ch-1 retired
        if (ch + 2 < 36)
            prefetch_chunk(Wst + ((ch + 2) % 3) * 4096, w2, (ch + 2) * 64, tid);
        cp_commit();           // always commit (possibly empty) to keep count

        const unsigned* W2u = (const unsigned*)(Wst + (ch % 3) * 4096);
        const int jbase = ch * 64;
        const int swz = qd << 3;

#pragma unroll
        for (int h2 = 0; h2 < 2; h2++) {
            // w-chunk half: cbuf[n][{r0c0,r0c1,r1c0,r1c1}], bias-initialized
            float c[4][4];
#pragma unroll
            for (int n = 0; n < 4; n++) {
                const float bb0 = b2a[jbase + (h2 * 4 + n) * 8 + 2 * qd];
                const float bb1 = b2a[jbase + (h2 * 4 + n) * 8 + 2 * qd + 1];
                c[n][0] = bb0; c[n][1] = bb1; c[n][2] = bb0; c[n][3] = bb1;
            }
#pragma unroll
            for (int ks = 0; ks < 8; ks++) {
                const int k0 = ks * 8 + qd;
#pragma unroll
                for (int n = 0; n < 4; n++) {
                    const int col = ((h2 * 4 + n) * 8 + gid) ^ swz;
                    const unsigned b0 = W2u[k0 * 64 + col];
                    const unsigned b1 = W2u[(k0 + 4) * 64 + col];
                    mma_tf32(c[n], a[ks], b0, b1);
                }
            }

            // region-aware contraction
            if (ch < 16) {                      // A (wa): u = 2ch + h2
#pragma unroll
                for (int r = 0; r < 2; r++) {
                    const int er = r ? er1 : er0;
                    const float y = x0_s[er * 33 + 2 * ch + h2] * sh0_s[er];
#pragma unroll
                    for (int n = 0; n < 4; n++) {
                        acc0[r][n][0] = fmaf(c[n][r * 2 + 0], y, acc0[r][n][0]);
                        acc0[r][n][1] = fmaf(c[n][r * 2 + 1], y, acc0[r][n][1]);
                    }
                }
            } else if (ch < 24) {               // C (wc): u = 4ch' + 2h2 + {0,1}
                const int chp = ch - 16;
#pragma unroll
                for (int r = 0; r < 2; r++) {
                    const int er = r ? er1 : er0;
                    const float xa = x0_s[er * 33 + 4 * chp + h2 * 2 + 0];
                    const float xb = x0_s[er * 33 + 4 * chp + h2 * 2 + 1];
#pragma unroll
                    for (int p = 0; p < 2; p++) {
                        cacc[r][p][0] = fmaf(c[p][r * 2 + 0], xa,
                                        fmaf(c[2 + p][r * 2 + 0], xb, cacc[r][p][0]));
                        cacc[r][p][1] = fmaf(c[p][r * 2 + 1], xa,
                                        fmaf(c[2 + p][r * 2 + 1], xb, cacc[r][p][1]));
                    }
                }
            } else if (ch < 28) {               // D (wd): u = 4ch' + 2h2 + t
                const int chp = ch - 24;
#pragma unroll
                for (int r = 0; r < 2; r++) {
                    const int er = r ? er1 : er0;
#pragma unroll
                    for (int t = 0; t < 2; t++) {
                        const int u = 4 * chp + h2 * 2 + t;
                        const float za = z1_s[er * 49 + u * 3 + 0];
                        const float zb = z1_s[er * 49 + u * 3 + 1];
                        const float zc = z1_s[er * 49 + u * 3 + 2];
#pragma unroll
                        for (int p = 0; p < 2; p++) {
                            const int n = t * 2 + p;
#pragma unroll
                            for (int j = 0; j < 2; j++) {
                                const float wv = c[n][r * 2 + j];
                                dacc[r][p][j][0] = fmaf(wv, za, dacc[r][p][j][0]);
                                dacc[r][p][j][1] = fmaf(wv, zb, dacc[r][p][j][1]);
                                dacc[r][p][j][2] = fmaf(wv, zc, dacc[r][p][j][2]);
                            }
                        }
                    }
                }
            } else {                            // B (wb): u = 2ch' + h2
                const int chp = ch - 28;
#pragma unroll
                for (int r = 0; r < 2; r++) {
                    const int er = r ? er1 : er0;
                    const float y = y1_s[er * 17 + 2 * chp + h2];
#pragma unroll
                    for (int n = 0; n < 4; n++) {
                        acc0[r][n][0] = fmaf(c[n][r * 2 + 0], y, acc0[r][n][0]);
                        acc0[r][n][1] = fmaf(c[n][r * 2 + 1], y, acc0[r][n][1]);
                    }
                }
            }
        }
    }

    // ---- writeouts ----
#pragma unroll
    for (int r = 0; r < 2; r++) {
        const int er = r ? er1 : er0;
        if (eBase + er < E) {
            const int node = dst_s[er];
            const float s1v = sh1_s[er * 3 + 0];
            const float s2v = sh1_s[er * 3 + 1];
            const float s3v = sh1_s[er * 3 + 2];
            // out1 (cols 32..79): v = p*8 + 2qd + j
#pragma unroll
            for (int p = 0; p < 2; p++)
#pragma unroll
                for (int j = 0; j < 2; j++) {
                    const int v = p * 8 + 2 * qd + j;
                    const float cc = cacc[r][p][j];
                    atomicAdd(&g_sums[node * 80 + 32 + v * 3 + 0],
                              NORM_V * (s1v * cc + dacc[r][p][j][0]));
                    atomicAdd(&g_sums[node * 80 + 32 + v * 3 + 1],
                              NORM_V * (s2v * cc + dacc[r][p][j][1]));
                    atomicAdd(&g_sums[node * 80 + 32 + v * 3 + 2],
                              NORM_V * (s3v * cc + dacc[r][p][j][2]));
                }
            // out0 (cols 0..31)
#pragma unroll
            for (int n = 0; n < 4; n++) {
                const int col = n * 8 + 2 * qd;
                atomicAdd(&g_sums[node * 80 + col],     NORM_V * acc0[r][n][0]);
                atomicAdd(&g_sums[node * 80 + col + 1], NORM_V * acc0[r][n][1]);
            }
            if (qd == 0) atomicAdd(&g_cnt[node], 1.0f);
        }
    }
}

// ---------------------------------------------------------------------------
// residual + mean; also restores g_sums/g_cnt to zero (graph-replay safe).
// blockDim = 160 (2 nodes per block, node never splits across blocks)
// ---------------------------------------------------------------------------
__global__ void final_kernel(
    int n_nodes,
    const float* __restrict__ x_dst,
    const float* __restrict__ rw0,
    const float* __restrict__ rw1,
    float* __restrict__ out)
{
    __shared__ float cs[2];
    const int local = threadIdx.x / 80;
    const int j     = threadIdx.x - local * 80;
    const int n     = blockIdx.x * 2 + local;
    const bool ok   = (n < n_nodes);

    if (ok && j == 0) cs[local] = g_cnt[n];
    __syncthreads();
    if (!ok) return;

    float res;
    if (j < 32) {
        float acc = 0.f;
#pragma unroll
        for (int u = 0; u < 32; u++)
            acc = fmaf(x_dst[n * 80 + u], rw0[u * 32 + j], acc);
        res = acc * RSQRT32_V;
    } else {
        const int w = (j - 32) / 3;
        const int m = (j - 32) - 3 * w;
        float acc = 0.f;
#pragma unroll
        for (int u = 0; u < 16; u++)
            acc = fmaf(x_dst[n * 80 + 32 + u * 3 + m], rw1[u * 16 + w], acc);
        res = acc * 0.25f;
    }
    const int idx = n * 80 + j;
    const float c = fmaxf(cs[local], 1.0f);
    out[idx] = res + g_sums[idx] / c;

    // restore zeros for next replay
    g_sums[idx] = 0.0f;
    if (j == 0) g_cnt[n] = 0.0f;
}

// ---------------------------------------------------------------------------
extern "C" void kernel_launch(void* const* d_in, const int* in_sizes, int n_in,
                              void* d_out, int out_size)
{
    const int*   dst       = (const int*)  d_in[0];
    const float* x_src     = (const float*)d_in[1];
    const float* x_dst     = (const float*)d_in[2];
    const float* sh        = (const float*)d_in[3];
    const float* edge_attr = (const float*)d_in[4];
    const float* w1        = (const float*)d_in[5];
    const float* b1        = (const float*)d_in[6];
    const float* w2        = (const float*)d_in[7];
    const float* b2        = (const float*)d_in[8];
    const float* rw0       = (const float*)d_in[9];
    const float* rw1       = (const float*)d_in[10];
    float* out = (float*)d_out;

    const int E       = in_sizes[0];
    const int n_nodes = in_sizes[2] / OUT_DIM;

    cudaFuncSetAttribute(edge_kernel,
                         cudaFuncAttributeMaxDynamicSharedMemorySize,
                         SMEM_BYTES);

    edge_kernel<<<(E + 255) / 256, 512, SMEM_BYTES>>>(
        E, dst, x_src, sh, edge_attr, w1, b1, w2, b2);
    final_kernel<<<(n_nodes + 1) / 2, 160>>>(
        n_nodes, x_dst, rw0, rw1, out);
}

// round 4
// speedup vs baseline: 1.0942x; 1.0942x over previous
#include <cuda_runtime.h>

// ---------------------------------------------------------------------------
// Conv_2259152798130 — fused e3nn edge conv.
// R4: tf32 mma + cp.async double-pipelined 32-col sub-chunks, 2 CTAs/SM.
//   h = relu(edge_attr @ W1 + b1)          [E,64]
//   w = h @ W2 + b2                        [E,2304]  (tf32 mma, never stored)
//   region-aware contraction -> msg[E,80] -> atomic segment sum
//   out = residual + segment_mean   (final_kernel also re-zeroes scratch)
// ---------------------------------------------------------------------------

#define NN       10000
#define OUT_DIM  80
#define NORM_V        0.14433756729740643f   // 1/sqrt(48)
#define INV_SQRT3_V   0.57735026918962576f
#define RSQRT32_V     0.17677669529663687f   // 1/sqrt(32)

// zero-initialized at module load; final_kernel restores zeros each run
__device__ float g_sums[NN * OUT_DIM];
__device__ float g_cnt[NN];

__device__ __forceinline__ float ftf32(float x) {
    float r;
    asm("cvt.rna.tf32.f32 %0, %1;" : "=f"(r) : "f"(x));
    return r;
}

__device__ __forceinline__ void mma_tf32(float c[4], const unsigned a[4],
                                         unsigned b0, unsigned b1) {
    asm volatile(
        "mma.sync.aligned.m16n8k8.row.col.f32.tf32.tf32.f32 "
        "{%0,%1,%2,%3}, {%4,%5,%6,%7}, {%8,%9}, {%0,%1,%2,%3};"
        : "+f"(c[0]), "+f"(c[1]), "+f"(c[2]), "+f"(c[3])
        : "r"(a[0]), "r"(a[1]), "r"(a[2]), "r"(a[3]), "r"(b0), "r"(b1));
}

__device__ __forceinline__ void cp_commit() {
    asm volatile("cp.async.commit_group;" ::: "memory");
}
template <int N>
__device__ __forceinline__ void cp_wait() {
    asm volatile("cp.async.wait_group %0;" :: "n"(N) : "memory");
}

// prefetch one 64k x 32col W2 sub-chunk (raw fp32, XOR swizzle) + 32 b2 floats
__device__ __forceinline__ void prefetch_sub(
    float* wbuf, float* bbuf,
    const float* __restrict__ w2, const float* __restrict__ b2,
    int j0, int tid)
{
    // 512 float4 over 256 threads (2 each): i -> k = i>>3, c = (i&7)*4
#pragma unroll
    for (int t = 0; t < 2; t++) {
        const int i = tid + t * 256;
        const int k = i >> 3;
        const int c = (i & 7) << 2;
        unsigned dst = (unsigned)__cvta_generic_to_shared(
            wbuf + k * 32 + (c ^ ((k & 3) << 3)));
        const float* src = w2 + k * 2304 + j0 + c;
        asm volatile("cp.async.cg.shared.global [%0], [%1], 16;"
                     :: "r"(dst), "l"(src));
    }
    if (tid < 8) {
        unsigned dst = (unsigned)__cvta_generic_to_shared(bbuf + tid * 4);
        const float* src = b2 + j0 + tid * 4;
        asm volatile("cp.async.cg.shared.global [%0], [%1], 16;"
                     :: "r"(dst), "l"(src));
    }
}

// ---------------------------------------------------------------------------
// Shared layout (floats), 128 edges/block, total 28256 floats = 113024 B
//   H_s   [128][68]   @ 0       (h, tf32-rounded)
//   Wst   [3][64][32] @ 8704    (cp.async stages; W1 aliased in phase 0)
//   b2st  [3][32]     @ 14848
//   x0_s  [128][33]   @ 14944
//   y1_s  [128][17]   @ 19168
//   z1_s  [128][49]   @ 21344
//   sh0_s [128]       @ 27616
//   sh1_s [128][3]    @ 27744
//   dst_s [128] int   @ 28128
// ---------------------------------------------------------------------------
#define SMEM_BYTES (28256 * 4)

__global__ __launch_bounds__(256, 2) void edge_kernel(
    int E,
    const int*   __restrict__ dst,
    const float* __restrict__ x_src,
    const float* __restrict__ sh,
    const float* __restrict__ edge_attr,
    const float* __restrict__ w1,
    const float* __restrict__ b1,
    const float* __restrict__ w2,
    const float* __restrict__ b2)
{
    extern __shared__ float smem[];
    float* H_s   = smem;
    float* Wst   = smem + 8704;
    float* b2st  = smem + 14848;
    float* x0_s  = smem + 14944;
    float* y1_s  = smem + 19168;
    float* z1_s  = smem + 21344;
    float* sh0_s = smem + 27616;
    float* sh1_s = smem + 27744;
    int*   dst_s = (int*)(smem + 28128);
    float* W1_s  = Wst;                    // phase-0 alias (2048 <= 6144)

    const int tid   = threadIdx.x;
    const int eBase = blockIdx.x * 128;
    const int e     = tid & 127;
    const int half  = tid >> 7;
    const int ge    = eBase + e;
    const bool valid = (ge < E);

    // ---- Phase 0: stage W1, per-edge features ----
    for (int i = tid; i < 512; i += 256)
        ((float4*)W1_s)[i] = ((const float4*)w1)[i];

    if (half == 0) {   // one thread per edge
        dst_s[e] = valid ? dst[ge] : 0;
        float s0 = 0.f, s1 = 0.f, s2 = 0.f, s3 = 0.f;
        if (valid) {
            const float4 shv = *(const float4*)&sh[ge * 4];
            s0 = shv.x; s1 = shv.y; s2 = shv.z; s3 = shv.w;
        }
        sh0_s[e] = s0;
        sh1_s[e * 3 + 0] = s1; sh1_s[e * 3 + 1] = s2; sh1_s[e * 3 + 2] = s3;
#pragma unroll
        for (int q = 0; q < 8; q++) {
            float4 v = valid ? ((const float4*)&x_src[ge * 80])[q]
                             : make_float4(0.f, 0.f, 0.f, 0.f);
            x0_s[e * 33 + q * 4 + 0] = v.x;
            x0_s[e * 33 + q * 4 + 1] = v.y;
            x0_s[e * 33 + q * 4 + 2] = v.z;
            x0_s[e * 33 + q * 4 + 3] = v.w;
        }
#pragma unroll
        for (int u = 0; u < 16; u++) {
            float a = 0.f, b = 0.f, c = 0.f;
            if (valid) {
                a = x_src[ge * 80 + 32 + u * 3 + 0];
                b = x_src[ge * 80 + 32 + u * 3 + 1];
                c = x_src[ge * 80 + 32 + u * 3 + 2];
            }
            y1_s[e * 17 + u] = INV_SQRT3_V * (a * s1 + b * s2 + c * s3);
            z1_s[e * 49 + u * 3 + 0] = a * s0;
            z1_s[e * 49 + u * 3 + 1] = b * s0;
            z1_s[e * 49 + u * 3 + 2] = c * s0;
        }
    }

    float attr[32];
#pragma unroll
    for (int q = 0; q < 8; q++) {
        float4 v = valid ? ((const float4*)&edge_attr[ge * 32])[q]
                         : make_float4(0.f, 0.f, 0.f, 0.f);
        attr[q * 4 + 0] = v.x; attr[q * 4 + 1] = v.y;
        attr[q * 4 + 2] = v.z; attr[q * 4 + 3] = v.w;
    }
    __syncthreads();

    // layer-1 MLP: each half computes 32 of the 64 h outputs of edge e
#pragma unroll 2
    for (int jj = 0; jj < 32; jj++) {
        const int j = half * 32 + jj;
        float acc = __ldg(&b1[j]);
#pragma unroll
        for (int i = 0; i < 32; i++)
            acc = fmaf(attr[i], W1_s[i * 64 + j], acc);
        H_s[e * 68 + j] = ftf32(fmaxf(acc, 0.0f));
    }
    __syncthreads();   // H done; W1 alias may now be overwritten

    // ---- kick off cp.async pipeline ----
    prefetch_sub(Wst,        b2st,      w2, b2, 0,  tid); cp_commit();
    prefetch_sub(Wst + 2048, b2st + 32, w2, b2, 32, tid); cp_commit();

    // ---- A fragments (sub-chunk-invariant) ----
    const int lane = tid & 31;
    const int warp = tid >> 5;          // 0..7 -> edges warp*16 .. +15
    const int gid  = lane >> 2;
    const int qd   = lane & 3;
    const int er0  = warp * 16 + gid;
    const int er1  = er0 + 8;
    const int swz  = qd << 3;

    unsigned a[8][4];
#pragma unroll
    for (int ks = 0; ks < 8; ks++) {
        a[ks][0] = __float_as_uint(H_s[er0 * 68 + ks * 8 + qd]);
        a[ks][1] = __float_as_uint(H_s[er1 * 68 + ks * 8 + qd]);
        a[ks][2] = __float_as_uint(H_s[er0 * 68 + ks * 8 + qd + 4]);
        a[ks][3] = __float_as_uint(H_s[er1 * 68 + ks * 8 + qd + 4]);
    }

    // accumulators
    float acc0[2][4][2];
    float cacc[2][2][2];
    float dacc[2][2][2][3];
#pragma unroll
    for (int r = 0; r < 2; r++) {
#pragma unroll
        for (int n = 0; n < 4; n++) { acc0[r][n][0] = 0.f; acc0[r][n][1] = 0.f; }
#pragma unroll
        for (int p = 0; p < 2; p++) {
            cacc[r][p][0] = 0.f; cacc[r][p][1] = 0.f;
#pragma unroll
            for (int j = 0; j < 2; j++) {
                dacc[r][p][j][0] = 0.f; dacc[r][p][j][1] = 0.f; dacc[r][p][j][2] = 0.f;
            }
        }
    }

    // ---- main pipelined loop: 72 sub-chunks of 32 columns ----
#pragma unroll 1
    for (int s = 0; s < 72; s++) {
        cp_wait<1>();          // sub-chunk s complete (own thread)
        __syncthreads();       // chunk s visible to all; buf (s+2)%3 free
        if (s + 2 < 72)
            prefetch_sub(Wst + ((s + 2) % 3) * 2048, b2st + ((s + 2) % 3) * 32,
                         w2, b2, (s + 2) * 32, tid);
        cp_commit();           // always commit to keep group count

        const int sb = (s % 3);
        const unsigned* W2u = (const unsigned*)(Wst + sb * 2048);
        const float*    bb  = b2st + sb * 32;

        // w sub-chunk: c[n][{r0c0,r0c1,r1c0,r1c1}], bias-initialized
        float c[4][4];
#pragma unroll
        for (int n = 0; n < 4; n++) {
            const float bb0 = bb[n * 8 + 2 * qd];
            const float bb1 = bb[n * 8 + 2 * qd + 1];
            c[n][0] = bb0; c[n][1] = bb1; c[n][2] = bb0; c[n][3] = bb1;
        }
#pragma unroll
        for (int ks = 0; ks < 8; ks++) {
            const int k0 = ks * 8 + qd;
#pragma unroll
            for (int n = 0; n < 4; n++) {
                const int col = (n * 8 + gid) ^ swz;
                const unsigned b0 = W2u[k0 * 32 + col];
                const unsigned b1 = W2u[(k0 + 4) * 32 + col];
                mma_tf32(c[n], a[ks], b0, b1);
            }
        }

        // region-aware contraction (32 cols per sub-chunk)
        if (s < 32) {                       // A (wa): u = s
#pragma unroll
            for (int r = 0; r < 2; r++) {
                const int er = r ? er1 : er0;
                const float y = x0_s[er * 33 + s] * sh0_s[er];
#pragma unroll
                for (int n = 0; n < 4; n++) {
                    acc0[r][n][0] = fmaf(c[n][r * 2 + 0], y, acc0[r][n][0]);
                    acc0[r][n][1] = fmaf(c[n][r * 2 + 1], y, acc0[r][n][1]);
                }
            }
        } else if (s < 48) {                // C (wc): u = 2s' + {0,1}
            const int sp = s - 32;
#pragma unroll
            for (int r = 0; r < 2; r++) {
                const int er = r ? er1 : er0;
                const float xa = x0_s[er * 33 + 2 * sp + 0];
                const float xb = x0_s[er * 33 + 2 * sp + 1];
#pragma unroll
                for (int p = 0; p < 2; p++) {
                    cacc[r][p][0] = fmaf(c[p][r * 2 + 0], xa,
                                    fmaf(c[2 + p][r * 2 + 0], xb, cacc[r][p][0]));
                    cacc[r][p][1] = fmaf(c[p][r * 2 + 1], xa,
                                    fmaf(c[2 + p][r * 2 + 1], xb, cacc[r][p][1]));
                }
            }
        } else if (s < 56) {                // D (wd): u = 2s' + t
            const int sp = s - 48;
#pragma unroll
            for (int r = 0; r < 2; r++) {
                const int er = r ? er1 : er0;
#pragma unroll
                for (int t = 0; t < 2; t++) {
                    const int u = 2 * sp + t;
                    const float za = z1_s[er * 49 + u * 3 + 0];
                    const float zb = z1_s[er * 49 + u * 3 + 1];
                    const float zc = z1_s[er * 49 + u * 3 + 2];
#pragma unroll
                    for (int p = 0; p < 2; p++) {
                        const int n = t * 2 + p;
#pragma unroll
                        for (int j = 0; j < 2; j++) {
                            const float wv = c[n][r * 2 + j];
                            dacc[r][p][j][0] = fmaf(wv, za, dacc[r][p][j][0]);
                            dacc[r][p][j][1] = fmaf(wv, zb, dacc[r][p][j][1]);
                            dacc[r][p][j][2] = fmaf(wv, zc, dacc[r][p][j][2]);
                        }
                    }
                }
            }
        } else {                            // B (wb): u = s - 56
            const int u = s - 56;
#pragma unroll
            for (int r = 0; r < 2; r++) {
                const int er = r ? er1 : er0;
                const float y = y1_s[er * 17 + u];
#pragma unroll
                for (int n = 0; n < 4; n++) {
                    acc0[r][n][0] = fmaf(c[n][r * 2 + 0], y, acc0[r][n][0]);
                    acc0[r][n][1] = fmaf(c[n][r * 2 + 1], y, acc0[r][n][1]);
                }
            }
        }
    }

    // ---- writeouts ----
#pragma unroll
    for (int r = 0; r < 2; r++) {
        const int er = r ? er1 : er0;
        if (eBase + er < E) {
            const int node = dst_s[er];
            const float s1v = sh1_s[er * 3 + 0];
            const float s2v = sh1_s[er * 3 + 1];
            const float s3v = sh1_s[er * 3 + 2];
            // out1 (cols 32..79): v = p*8 + 2qd + j
#pragma unroll
            for (int p = 0; p < 2; p++)
#pragma unroll
                for (int j = 0; j < 2; j++) {
                    const int v = p * 8 + 2 * qd + j;
                    const float cc = cacc[r][p][j];
                    atomicAdd(&g_sums[node * 80 + 32 + v * 3 + 0],
                              NORM_V * (s1v * cc + dacc[r][p][j][0]));
                    atomicAdd(&g_sums[node * 80 + 32 + v * 3 + 1],
                              NORM_V * (s2v * cc + dacc[r][p][j][1]));
                    atomicAdd(&g_sums[node * 80 + 32 + v * 3 + 2],
                              NORM_V * (s3v * cc + dacc[r][p][j][2]));
                }
            // out0 (cols 0..31)
#pragma unroll
            for (int n = 0; n < 4; n++) {
                const int col = n * 8 + 2 * qd;
                atomicAdd(&g_sums[node * 80 + col],     NORM_V * acc0[r][n][0]);
                atomicAdd(&g_sums[node * 80 + col + 1], NORM_V * acc0[r][n][1]);
            }
            if (qd == 0) atomicAdd(&g_cnt[node], 1.0f);
        }
    }
}

// ---------------------------------------------------------------------------
// residual + mean; also restores g_sums/g_cnt to zero (graph-replay safe).
// blockDim = 160 (2 nodes per block, node never splits across blocks)
// ---------------------------------------------------------------------------
__global__ void final_kernel(
    int n_nodes,
    const float* __restrict__ x_dst,
    const float* __restrict__ rw0,
    const float* __restrict__ rw1,
    float* __restrict__ out)
{
    __shared__ float cs[2];
    const int local = threadIdx.x / 80;
    const int j     = threadIdx.x - local * 80;
    const int n     = blockIdx.x * 2 + local;
    const bool ok   = (n < n_nodes);

    if (ok && j == 0) cs[local] = g_cnt[n];
    __syncthreads();
    if (!ok) return;

    float res;
    if (j < 32) {
        float acc = 0.f;
#pragma unroll
        for (int u = 0; u < 32; u++)
            acc = fmaf(x_dst[n * 80 + u], rw0[u * 32 + j], acc);
        res = acc * RSQRT32_V;
    } else {
        const int w = (j - 32) / 3;
        const int m = (j - 32) - 3 * w;
        float acc = 0.f;
#pragma unroll
        for (int u = 0; u < 16; u++)
            acc = fmaf(x_dst[n * 80 + 32 + u * 3 + m], rw1[u * 16 + w], acc);
        res = acc * 0.25f;
    }
    const int idx = n * 80 + j;
    const float c = fmaxf(cs[local], 1.0f);
    out[idx] = res + g_sums[idx] / c;

    // restore zeros for next replay
    g_sums[idx] = 0.0f;
    if (j == 0) g_cnt[n] = 0.0f;
}

// ---------------------------------------------------------------------------
extern "C" void kernel_launch(void* const* d_in, const int* in_sizes, int n_in,
                              void* d_out, int out_size)
{
    const int*   dst       = (const int*)  d_in[0];
    const float* x_src     = (const float*)d_in[1];
    const float* x_dst     = (const float*)d_in[2];
    const float* sh        = (const float*)d_in[3];
    const float* edge_attr = (const float*)d_in[4];
    const float* w1        = (const float*)d_in[5];
    const float* b1        = (const float*)d_in[6];
    const float* w2        = (const float*)d_in[7];
    const float* b2        = (const float*)d_in[8];
    const float* rw0       = (const float*)d_in[9];
    const float* rw1       = (const float*)d_in[10];
    float* out = (float*)d_out;

    const int E       = in_sizes[0];
    const int n_nodes = in_sizes[2] / OUT_DIM;

    cudaFuncSetAttribute(edge_kernel,
                         cudaFuncAttributeMaxDynamicSharedMemorySize,
                         SMEM_BYTES);

    edge_kernel<<<(E + 127) / 128, 256, SMEM_BYTES>>>(
        E, dst, x_src, sh, edge_attr, w1, b1, w2, b2);
    final_kernel<<<(n_nodes + 1) / 2, 160>>>(
        n_nodes, x_dst, rw0, rw1, out);
}

// round 5
// speedup vs baseline: 1.6350x; 1.4942x over previous
#include <cuda_runtime.h>
#include <cuda_fp16.h>

// ---------------------------------------------------------------------------
// Conv_2259152798130 — fused e3nn edge conv.
// R5: fp16 mma (m16n8k16, fp32 accum) + cp.async pipeline, 2 CTAs/SM.
//   W2 pre-packed to k-paired half2 by convert_w2 (device-global scratch).
//   h = relu(edge_attr @ W1 + b1)  -> fp16 pairs in smem
//   w = h @ W2 + b2  (fp16 mma, fp32 accum, never stored)
//   region-aware contraction -> msg[E,80] -> atomic segment sum
//   out = residual + segment_mean  (final_kernel re-zeroes scratch)
// ---------------------------------------------------------------------------

#define NN       10000
#define OUT_DIM  80
#define NORM_V        0.14433756729740643f   // 1/sqrt(48)
#define INV_SQRT3_V   0.57735026918962576f
#define RSQRT32_V     0.17677669529663687f   // 1/sqrt(32)

// zero-initialized at module load; final_kernel restores zeros each run
__device__ float g_sums[NN * OUT_DIM];
__device__ float g_cnt[NN];
// W2 packed as fp16 k-pairs: g_w2h[kp*2304 + n] = half2(w2[2kp][n], w2[2kp+1][n])
__device__ unsigned g_w2h[32 * 2304];

__global__ void convert_w2(const float* __restrict__ w2) {
    const int i = blockIdx.x * blockDim.x + threadIdx.x;
    if (i < 32 * 2304) {
        const int kp = i / 2304;
        const int n  = i - kp * 2304;
        const __half2 h2 = __halves2half2(
            __float2half_rn(w2[(2 * kp)     * 2304 + n]),
            __float2half_rn(w2[(2 * kp + 1) * 2304 + n]));
        g_w2h[i] = *(const unsigned*)&h2;
    }
}

// mma m16n8k16 fp16 -> fp32 accum (A row-major, B col-major)
__device__ __forceinline__ void mma_f16(float c[4], const unsigned a[4],
                                        unsigned b0, unsigned b1) {
    asm volatile(
        "mma.sync.aligned.m16n8k16.row.col.f32.f16.f16.f32 "
        "{%0,%1,%2,%3}, {%4,%5,%6,%7}, {%8,%9}, {%0,%1,%2,%3};"
        : "+f"(c[0]), "+f"(c[1]), "+f"(c[2]), "+f"(c[3])
        : "r"(a[0]), "r"(a[1]), "r"(a[2]), "r"(a[3]), "r"(b0), "r"(b1));
}

__device__ __forceinline__ void cp_commit() {
    asm volatile("cp.async.commit_group;" ::: "memory");
}
template <int N>
__device__ __forceinline__ void cp_wait() {
    asm volatile("cp.async.wait_group %0;" :: "n"(N) : "memory");
}

// prefetch one 32kp x 64col fp16-pair chunk (8 KB) + 64 b2 floats
__device__ __forceinline__ void prefetch_chunk(
    unsigned* wbuf, float* bbuf,
    const float* __restrict__ b2, int j0, int tid)
{
    // 512 x 16B over 256 threads (2 each): i -> kp = i>>4, c = (i&15)*4
#pragma unroll
    for (int t = 0; t < 2; t++) {
        const int i  = tid + t * 256;
        const int kp = i >> 4;
        const int c  = (i & 15) << 2;
        unsigned dst = (unsigned)__cvta_generic_to_shared(
            wbuf + kp * 64 + (c ^ ((kp & 3) << 3)));
        const unsigned* src = g_w2h + kp * 2304 + j0 + c;
        asm volatile("cp.async.cg.shared.global [%0], [%1], 16;"
                     :: "r"(dst), "l"(src));
    }
    if (tid < 16) {
        unsigned dst = (unsigned)__cvta_generic_to_shared(bbuf + tid * 4);
        const float* src = b2 + j0 + tid * 4;
        asm volatile("cp.async.cg.shared.global [%0], [%1], 16;"
                     :: "r"(dst), "l"(src));
    }
}

// ---------------------------------------------------------------------------
// Shared layout (4-byte units), 128 edges/block, total 23872 = 95488 B
//   Hu    [128][33] u32 @ 0      (h fp16 pairs)
//   Wst   [3][2048] u32 @ 4224   (fp16 W2 stages; W1 alias in phase 0)
//   b2st  [3][64]       @ 10368
//   x0_s  [128][33]     @ 10560
//   y1_s  [128][17]     @ 14784
//   z1_s  [128][49]     @ 16960
//   sh0_s [128]         @ 23232
//   sh1_s [128][3]      @ 23360
//   dst_s [128] int     @ 23744
// ---------------------------------------------------------------------------
#define SMEM_BYTES (23872 * 4)

__global__ __launch_bounds__(256, 2) void edge_kernel(
    int E,
    const int*   __restrict__ dst,
    const float* __restrict__ x_src,
    const float* __restrict__ sh,
    const float* __restrict__ edge_attr,
    const float* __restrict__ w1,
    const float* __restrict__ b1,
    const float* __restrict__ b2)
{
    extern __shared__ float smem[];
    unsigned* Hu   = (unsigned*)smem;
    unsigned* Wst  = (unsigned*)(smem + 4224);
    float* b2st  = smem + 10368;
    float* x0_s  = smem + 10560;
    float* y1_s  = smem + 14784;
    float* z1_s  = smem + 16960;
    float* sh0_s = smem + 23232;
    float* sh1_s = smem + 23360;
    int*   dst_s = (int*)(smem + 23744);
    float* W1_s  = (float*)Wst;            // phase-0 alias (2048 <= 6144)

    const int tid   = threadIdx.x;
    const int eBase = blockIdx.x * 128;
    const int e     = tid & 127;
    const int half  = tid >> 7;
    const int ge    = eBase + e;
    const bool valid = (ge < E);

    // ---- Phase 0: stage W1, per-edge features ----
    for (int i = tid; i < 512; i += 256)
        ((float4*)W1_s)[i] = ((const float4*)w1)[i];

    if (half == 0) {   // one thread per edge
        dst_s[e] = valid ? dst[ge] : 0;
        float s0 = 0.f, s1 = 0.f, s2 = 0.f, s3 = 0.f;
        if (valid) {
            const float4 shv = *(const float4*)&sh[ge * 4];
            s0 = shv.x; s1 = shv.y; s2 = shv.z; s3 = shv.w;
        }
        sh0_s[e] = s0;
        sh1_s[e * 3 + 0] = s1; sh1_s[e * 3 + 1] = s2; sh1_s[e * 3 + 2] = s3;
#pragma unroll
        for (int q = 0; q < 8; q++) {
            float4 v = valid ? ((const float4*)&x_src[ge * 80])[q]
                             : make_float4(0.f, 0.f, 0.f, 0.f);
            x0_s[e * 33 + q * 4 + 0] = v.x;
            x0_s[e * 33 + q * 4 + 1] = v.y;
            x0_s[e * 33 + q * 4 + 2] = v.z;
            x0_s[e * 33 + q * 4 + 3] = v.w;
        }
#pragma unroll
        for (int u = 0; u < 16; u++) {
            float a = 0.f, b = 0.f, c = 0.f;
            if (valid) {
                a = x_src[ge * 80 + 32 + u * 3 + 0];
                b = x_src[ge * 80 + 32 + u * 3 + 1];
                c = x_src[ge * 80 + 32 + u * 3 + 2];
            }
            y1_s[e * 17 + u] = INV_SQRT3_V * (a * s1 + b * s2 + c * s3);
            z1_s[e * 49 + u * 3 + 0] = a * s0;
            z1_s[e * 49 + u * 3 + 1] = b * s0;
            z1_s[e * 49 + u * 3 + 2] = c * s0;
        }
    }

    float attr[32];
#pragma unroll
    for (int q = 0; q < 8; q++) {
        float4 v = valid ? ((const float4*)&edge_attr[ge * 32])[q]
                         : make_float4(0.f, 0.f, 0.f, 0.f);
        attr[q * 4 + 0] = v.x; attr[q * 4 + 1] = v.y;
        attr[q * 4 + 2] = v.z; attr[q * 4 + 3] = v.w;
    }
    __syncthreads();

    // layer-1 MLP: each half computes 32 of the 64 h outputs (16 fp16 pairs)
#pragma unroll 2
    for (int t = 0; t < 16; t++) {
        const int j = half * 32 + 2 * t;
        float acc0 = __ldg(&b1[j]);
        float acc1 = __ldg(&b1[j + 1]);
#pragma unroll
        for (int i = 0; i < 32; i++) {
            acc0 = fmaf(attr[i], W1_s[i * 64 + j],     acc0);
            acc1 = fmaf(attr[i], W1_s[i * 64 + j + 1], acc1);
        }
        const __half2 h2 = __halves2half2(
            __float2half_rn(fmaxf(acc0, 0.0f)),
            __float2half_rn(fmaxf(acc1, 0.0f)));
        Hu[e * 33 + half * 16 + t] = *(const unsigned*)&h2;
    }
    __syncthreads();   // H done; W1 alias may now be overwritten

    // ---- kick off cp.async pipeline ----
    prefetch_chunk(Wst,        b2st,      b2, 0,  tid); cp_commit();
    prefetch_chunk(Wst + 2048, b2st + 64, b2, 64, tid); cp_commit();

    // ---- A fragments (chunk-invariant): 4 k-steps x 4 regs fp16x2 ----
    const int lane = tid & 31;
    const int warp = tid >> 5;          // 0..7 -> edges warp*16 .. +15
    const int gid  = lane >> 2;
    const int qd   = lane & 3;
    const int er0  = warp * 16 + gid;
    const int er1  = er0 + 8;
    const int swz  = qd << 3;

    unsigned a[4][4];
#pragma unroll
    for (int ks = 0; ks < 4; ks++) {
        a[ks][0] = Hu[er0 * 33 + 8 * ks + qd];
        a[ks][1] = Hu[er1 * 33 + 8 * ks + qd];
        a[ks][2] = Hu[er0 * 33 + 8 * ks + 4 + qd];
        a[ks][3] = Hu[er1 * 33 + 8 * ks + 4 + qd];
    }

    // accumulators
    float acc0[2][4][2];
    float cacc[2][2][2];
    float dacc[2][2][2][3];
#pragma unroll
    for (int r = 0; r < 2; r++) {
#pragma unroll
        for (int n = 0; n < 4; n++) { acc0[r][n][0] = 0.f; acc0[r][n][1] = 0.f; }
#pragma unroll
        for (int p = 0; p < 2; p++) {
            cacc[r][p][0] = 0.f; cacc[r][p][1] = 0.f;
#pragma unroll
            for (int j = 0; j < 2; j++) {
                dacc[r][p][j][0] = 0.f; dacc[r][p][j][1] = 0.f; dacc[r][p][j][2] = 0.f;
            }
        }
    }

    // ---- main pipelined loop over 36 column chunks of 64 ----
#pragma unroll 1
    for (int ch = 0; ch < 36; ch++) {
        cp_wait<1>();          // chunk ch resident (own thread's view)
        __syncthreads();       // visible to all; buffer (ch+2)%3 free
        if (ch + 2 < 36)
            prefetch_chunk(Wst + ((ch + 2) % 3) * 2048,
                           b2st + ((ch + 2) % 3) * 64,
                           b2, (ch + 2) * 64, tid);
        cp_commit();           // always commit to keep group count

        const unsigned* W2u = Wst + (ch % 3) * 2048;
        const float*    bb  = b2st + (ch % 3) * 64;

#pragma unroll
        for (int h2 = 0; h2 < 2; h2++) {
            // w half-chunk: c[n][{r0c0,r0c1,r1c0,r1c1}], bias-initialized
            float c[4][4];
#pragma unroll
            for (int n = 0; n < 4; n++) {
                const float bb0 = bb[(h2 * 4 + n) * 8 + 2 * qd];
                const float bb1 = bb[(h2 * 4 + n) * 8 + 2 * qd + 1];
                c[n][0] = bb0; c[n][1] = bb1; c[n][2] = bb0; c[n][3] = bb1;
            }
#pragma unroll
            for (int ks = 0; ks < 4; ks++) {
#pragma unroll
                for (int n = 0; n < 4; n++) {
                    const int col = (((h2 * 4 + n) * 8 + gid)) ^ swz;
                    const unsigned b0 = W2u[(8 * ks + qd)     * 64 + col];
                    const unsigned b1 = W2u[(8 * ks + 4 + qd) * 64 + col];
                    mma_f16(c[n], a[ks], b0, b1);
                }
            }

            // region-aware contraction
            if (ch < 16) {                      // A (wa): u = 2ch + h2
#pragma unroll
                for (int r = 0; r < 2; r++) {
                    const int er = r ? er1 : er0;
                    const float y = x0_s[er * 33 + 2 * ch + h2] * sh0_s[er];
#pragma unroll
                    for (int n = 0; n < 4; n++) {
                        acc0[r][n][0] = fmaf(c[n][r * 2 + 0], y, acc0[r][n][0]);
                        acc0[r][n][1] = fmaf(c[n][r * 2 + 1], y, acc0[r][n][1]);
                    }
                }
            } else if (ch < 24) {               // C (wc): u = 4ch' + 2h2 + {0,1}
                const int chp = ch - 16;
#pragma unroll
                for (int r = 0; r < 2; r++) {
                    const int er = r ? er1 : er0;
                    const float xa = x0_s[er * 33 + 4 * chp + h2 * 2 + 0];
                    const float xb = x0_s[er * 33 + 4 * chp + h2 * 2 + 1];
#pragma unroll
                    for (int p = 0; p < 2; p++) {
                        cacc[r][p][0] = fmaf(c[p][r * 2 + 0], xa,
                                        fmaf(c[2 + p][r * 2 + 0], xb, cacc[r][p][0]));
                        cacc[r][p][1] = fmaf(c[p][r * 2 + 1], xa,
                                        fmaf(c[2 + p][r * 2 + 1], xb, cacc[r][p][1]));
                    }
                }
            } else if (ch < 28) {               // D (wd): u = 4ch' + 2h2 + t
                const int chp = ch - 24;
#pragma unroll
                for (int r = 0; r < 2; r++) {
                    const int er = r ? er1 : er0;
#pragma unroll
                    for (int t = 0; t < 2; t++) {
                        const int u = 4 * chp + h2 * 2 + t;
                        const float za = z1_s[er * 49 + u * 3 + 0];
                        const float zb = z1_s[er * 49 + u * 3 + 1];
                        const float zc = z1_s[er * 49 + u * 3 + 2];
#pragma unroll
                        for (int p = 0; p < 2; p++) {
                            const int n = t * 2 + p;
#pragma unroll
                            for (int j = 0; j < 2; j++) {
                                const float wv = c[n][r * 2 + j];
                                dacc[r][p][j][0] = fmaf(wv, za, dacc[r][p][j][0]);
                                dacc[r][p][j][1] = fmaf(wv, zb, dacc[r][p][j][1]);
                                dacc[r][p][j][2] = fmaf(wv, zc, dacc[r][p][j][2]);
                            }
                        }
                    }
                }
            } else {                            // B (wb): u = 2ch' + h2
                const int chp = ch - 28;
#pragma unroll
                for (int r = 0; r < 2; r++) {
                    const int er = r ? er1 : er0;
                    const float y = y1_s[er * 17 + 2 * chp + h2];
#pragma unroll
                    for (int n = 0; n < 4; n++) {
                        acc0[r][n][0] = fmaf(c[n][r * 2 + 0], y, acc0[r][n][0]);
                        acc0[r][n][1] = fmaf(c[n][r * 2 + 1], y, acc0[r][n][1]);
                    }
                }
            }
        }
    }

    // ---- writeouts ----
#pragma unroll
    for (int r = 0; r < 2; r++) {
        const int er = r ? er1 : er0;
        if (eBase + er < E) {
            const int node = dst_s[er];
            const float s1v = sh1_s[er * 3 + 0];
            const float s2v = sh1_s[er * 3 + 1];
            const float s3v = sh1_s[er * 3 + 2];
            // out1 (cols 32..79): v = p*8 + 2qd + j
#pragma unroll
            for (int p = 0; p < 2; p++)
#pragma unroll
                for (int j = 0; j < 2; j++) {
                    const int v = p * 8 + 2 * qd + j;
                    const float cc = cacc[r][p][j];
                    atomicAdd(&g_sums[node * 80 + 32 + v * 3 + 0],
                              NORM_V * (s1v * cc + dacc[r][p][j][0]));
                    atomicAdd(&g_sums[node * 80 + 32 + v * 3 + 1],
                              NORM_V * (s2v * cc + dacc[r][p][j][1]));
                    atomicAdd(&g_sums[node * 80 + 32 + v * 3 + 2],
                              NORM_V * (s3v * cc + dacc[r][p][j][2]));
                }
            // out0 (cols 0..31)
#pragma unroll
            for (int n = 0; n < 4; n++) {
                const int col = n * 8 + 2 * qd;
                atomicAdd(&g_sums[node * 80 + col],     NORM_V * acc0[r][n][0]);
                atomicAdd(&g_sums[node * 80 + col + 1], NORM_V * acc0[r][n][1]);
            }
            if (qd == 0) atomicAdd(&g_cnt[node], 1.0f);
        }
    }
}

// ---------------------------------------------------------------------------
// residual + mean; also restores g_sums/g_cnt to zero (graph-replay safe).
// ---------------------------------------------------------------------------
__global__ void final_kernel(
    int n_nodes,
    const float* __restrict__ x_dst,
    const float* __restrict__ rw0,
    const float* __restrict__ rw1,
    float* __restrict__ out)
{
    __shared__ float cs[2];
    const int local = threadIdx.x / 80;
    const int j     = threadIdx.x - local * 80;
    const int n     = blockIdx.x * 2 + local;
    const bool ok   = (n < n_nodes);

    if (ok && j == 0) cs[local] = g_cnt[n];
    __syncthreads();
    if (!ok) return;

    float res;
    if (j < 32) {
        float acc = 0.f;
#pragma unroll
        for (int u = 0; u < 32; u++)
            acc = fmaf(x_dst[n * 80 + u], rw0[u * 32 + j], acc);
        res = acc * RSQRT32_V;
    } else {
        const int w = (j - 32) / 3;
        const int m = (j - 32) - 3 * w;
        float acc = 0.f;
#pragma unroll
        for (int u = 0; u < 16; u++)
            acc = fmaf(x_dst[n * 80 + 32 + u * 3 + m], rw1[u * 16 + w], acc);
        res = acc * 0.25f;
    }
    const int idx = n * 80 + j;
    const float c = fmaxf(cs[local], 1.0f);
    out[idx] = res + g_sums[idx] / c;

    // restore zeros for next replay
    g_sums[idx] = 0.0f;
    if (j == 0) g_cnt[n] = 0.0f;
}

// ---------------------------------------------------------------------------
extern "C" void kernel_launch(void* const* d_in, const int* in_sizes, int n_in,
                              void* d_out, int out_size)
{
    const int*   dst       = (const int*)  d_in[0];
    const float* x_src     = (const float*)d_in[1];
    const float* x_dst     = (const float*)d_in[2];
    const float* sh        = (const float*)d_in[3];
    const float* edge_attr = (const float*)d_in[4];
    const float* w1        = (const float*)d_in[5];
    const float* b1        = (const float*)d_in[6];
    const float* w2        = (const float*)d_in[7];
    const float* b2        = (const float*)d_in[8];
    const float* rw0       = (const float*)d_in[9];
    const float* rw1       = (const float*)d_in[10];
    float* out = (float*)d_out;

    const int E       = in_sizes[0];
    const int n_nodes = in_sizes[2] / OUT_DIM;

    cudaFuncSetAttribute(edge_kernel,
                         cudaFuncAttributeMaxDynamicSharedMemorySize,
                         SMEM_BYTES);

    convert_w2<<<(32 * 2304 + 255) / 256, 256>>>(w2);
    edge_kernel<<<(E + 127) / 128, 256, SMEM_BYTES>>>(
        E, dst, x_src, sh, edge_attr, w1, b1, b2);
    final_kernel<<<(n_nodes + 1) / 2, 160>>>(
        n_nodes, x_dst, rw0, rw1, out);
}

// round 7
// speedup vs baseline: 1.7354x; 1.0614x over previous
#include <cuda_runtime.h>
#include <cuda_fp16.h>

// ---------------------------------------------------------------------------
// Conv_2259152798130 — fused e3nn edge conv.
// R7: fp16 mma (m16n8k16) + cp.async pipeline + ldmatrix B fragments.
//   W2 pre-packed to fp16 [col j][64 k's contiguous, 128B rows] (coalesced
//   transpose kernel). Edge kernel stages 64-col chunks as [n][k] rows with
//   seg^=(n&7) swizzle; B fragments come from ldmatrix.m8n8.x4 (conflict-free).
//   h = relu(edge_attr @ W1 + b1) -> fp16 pairs in smem
//   w = h @ W2 + b2 (fp16 mma, fp32 accum, never stored)
//   region-aware contraction -> msg[E,80] -> atomic segment sum
//   out = residual + segment_mean  (final_kernel re-zeroes scratch)
// ---------------------------------------------------------------------------

#define NN       10000
#define OUT_DIM  80
#define NORM_V        0.14433756729740643f   // 1/sqrt(48)
#define INV_SQRT3_V   0.57735026918962576f
#define RSQRT32_V     0.17677669529663687f   // 1/sqrt(32)

// zero-initialized at module load; final_kernel restores zeros each run
__device__ float g_sums[NN * OUT_DIM];
__device__ float g_cnt[NN];
// W2 as fp16: row j (output col, 0..2303) holds its 64 k-values as 32 half2
// (k-major, 128 bytes per row) -> g_w2h[j*32 + kp]
__device__ unsigned g_w2h[2304 * 32];

// tiled transpose+convert: coalesced reads of w2 and coalesced writes of g_w2h
__global__ void convert_w2(const float* __restrict__ w2) {
    __shared__ float s[64][33];
    const int x  = threadIdx.x;            // 0..31
    const int y  = threadIdx.y;            // 0..7
    const int j0 = blockIdx.x * 32;
    // load 64 k-rows x 32 cols, coalesced in j
#pragma unroll
    for (int r = 0; r < 8; r++) {
        const int k = y * 8 + r;
        s[k][x] = w2[k * 2304 + j0 + x];
    }
    __syncthreads();
    // write: lane = kp (coalesced 128B rows of g_w2h)
#pragma unroll
    for (int q = 0; q < 4; q++) {
        const int jj = y * 4 + q;
        const __half2 h2 = __halves2half2(
            __float2half_rn(s[2 * x][jj]),
            __float2half_rn(s[2 * x + 1][jj]));
        g_w2h[(j0 + jj) * 32 + x] = *(const unsigned*)&h2;
    }
}

// mma m16n8k16 fp16 -> fp32 accum (A row-major, B col-major)
__device__ __forceinline__ void mma_f16(float c[4], const unsigned a[4],
                                        unsigned b0, unsigned b1) {
    asm volatile(
        "mma.sync.aligned.m16n8k16.row.col.f32.f16.f16.f32 "
        "{%0,%1,%2,%3}, {%4,%5,%6,%7}, {%8,%9}, {%0,%1,%2,%3};"
        : "+f"(c[0]), "+f"(c[1]), "+f"(c[2]), "+f"(c[3])
        : "r"(a[0]), "r"(a[1]), "r"(a[2]), "r"(a[3]), "r"(b0), "r"(b1));
}

__device__ __forceinline__ void ldsm_x4(unsigned& r0, unsigned& r1,
                                        unsigned& r2, unsigned& r3,
                                        unsigned addr) {
    asm volatile("ldmatrix.sync.aligned.m8n8.x4.shared.b16 {%0,%1,%2,%3}, [%4];"
                 : "=r"(r0), "=r"(r1), "=r"(r2), "=r"(r3) : "r"(addr));
}

__device__ __forceinline__ void cp_commit() {
    asm volatile("cp.async.commit_group;" ::: "memory");
}
template <int N>
__device__ __forceinline__ void cp_wait() {
    asm volatile("cp.async.wait_group %0;" :: "n"(N) : "memory");
}

// prefetch one chunk: 64 rows (out cols) x 128B (64 fp16 k's), swizzled,
// plus 64 b2 floats
__device__ __forceinline__ void prefetch_chunk(
    unsigned wbuf_b, float* bbuf, const float* __restrict__ b2,
    int ch, int tid)
{
    // 512 x 16B segments over 256 threads (2 each)
#pragma unroll
    for (int t = 0; t < 2; t++) {
        const int i = tid + t * 256;       // 0..511
        const int n = i >> 3;              // row (out col) 0..63
        const int s = i & 7;               // 16B segment within row
        const unsigned dst = wbuf_b + (unsigned)(n * 128 + ((s ^ (n & 7)) << 4));
        const char* src = (const char*)g_w2h + (size_t)(ch * 64 + n) * 128 + s * 16;
        asm volatile("cp.async.cg.shared.global [%0], [%1], 16;"
                     :: "r"(dst), "l"(src));
    }
    if (tid < 16) {
        unsigned dst;
        asm("{ .reg .u64 t; cvta.to.shared.u64 t, %1; cvt.u32.u64 %0, t; }"
            : "=r"(dst) : "l"(bbuf + tid * 4));
        const float* src = b2 + ch * 64 + tid * 4;
        asm volatile("cp.async.cg.shared.global [%0], [%1], 16;"
                     :: "r"(dst), "l"(src));
    }
}

// ---------------------------------------------------------------------------
// Shared layout (4-byte units), 128 edges/block, total 23872 = 95488 B
//   Hu    [128][33] u32 @ 0      (h fp16 pairs)
//   Wst   [3][2048] u32 @ 4224   (fp16 W2 stages, [n][k] swizzled; W1 alias)
//   b2st  [3][64]       @ 10368
//   x0_s  [128][33]     @ 10560
//   y1_s  [128][17]     @ 14784
//   z1_s  [128][49]     @ 16960
//   sh0_s [128]         @ 23232
//   sh1_s [128][3]      @ 23360
//   dst_s [128] int     @ 23744
// ---------------------------------------------------------------------------
#define SMEM_BYTES (23872 * 4)

__global__ __launch_bounds__(256, 2) void edge_kernel(
    int E,
    const int*   __restrict__ dst,
    const float* __restrict__ x_src,
    const float* __restrict__ sh,
    const float* __restrict__ edge_attr,
    const float* __restrict__ w1,
    const float* __restrict__ b1,
    const float* __restrict__ b2)
{
    extern __shared__ float smem[];
    unsigned* Hu   = (unsigned*)smem;
    float* b2st  = smem + 10368;
    float* x0_s  = smem + 10560;
    float* y1_s  = smem + 14784;
    float* z1_s  = smem + 16960;
    float* sh0_s = smem + 23232;
    float* sh1_s = smem + 23360;
    int*   dst_s = (int*)(smem + 23744);
    float* W1_s  = smem + 4224;            // phase-0 alias (2048 <= 6144)

    unsigned wst_b;                        // byte smem addr of Wst
    asm("{ .reg .u64 t; cvta.to.shared.u64 t, %1; cvt.u32.u64 %0, t; }"
        : "=r"(wst_b) : "l"(smem + 4224));

    const int tid   = threadIdx.x;
    const int eBase = blockIdx.x * 128;
    const int e     = tid & 127;
    const int half  = tid >> 7;
    const int ge    = eBase + e;
    const bool valid = (ge < E);

    // ---- Phase 0: stage W1, per-edge features ----
    for (int i = tid; i < 512; i += 256)
        ((float4*)W1_s)[i] = ((const float4*)w1)[i];

    if (half == 0) {   // one thread per edge
        dst_s[e] = valid ? dst[ge] : 0;
        float s0 = 0.f, s1 = 0.f, s2 = 0.f, s3 = 0.f;
        if (valid) {
            const float4 shv = *(const float4*)&sh[ge * 4];
            s0 = shv.x; s1 = shv.y; s2 = shv.z; s3 = shv.w;
        }
        sh0_s[e] = s0;
        sh1_s[e * 3 + 0] = s1; sh1_s[e * 3 + 1] = s2; sh1_s[e * 3 + 2] = s3;
#pragma unroll
        for (int q = 0; q < 8; q++) {
            float4 v = valid ? ((const float4*)&x_src[ge * 80])[q]
                             : make_float4(0.f, 0.f, 0.f, 0.f);
            x0_s[e * 33 + q * 4 + 0] = v.x;
            x0_s[e * 33 + q * 4 + 1] = v.y;
            x0_s[e * 33 + q * 4 + 2] = v.z;
            x0_s[e * 33 + q * 4 + 3] = v.w;
        }
#pragma unroll
        for (int u = 0; u < 16; u++) {
            float a = 0.f, b = 0.f, c = 0.f;
            if (valid) {
                a = x_src[ge * 80 + 32 + u * 3 + 0];
                b = x_src[ge * 80 + 32 + u * 3 + 1];
                c = x_src[ge * 80 + 32 + u * 3 + 2];
            }
            y1_s[e * 17 + u] = INV_SQRT3_V * (a * s1 + b * s2 + c * s3);
            z1_s[e * 49 + u * 3 + 0] = a * s0;
            z1_s[e * 49 + u * 3 + 1] = b * s0;
            z1_s[e * 49 + u * 3 + 2] = c * s0;
        }
    }

    float attr[32];
#pragma unroll
    for (int q = 0; q < 8; q++) {
        float4 v = valid ? ((const float4*)&edge_attr[ge * 32])[q]
                         : make_float4(0.f, 0.f, 0.f, 0.f);
        attr[q * 4 + 0] = v.x; attr[q * 4 + 1] = v.y;
        attr[q * 4 + 2] = v.z; attr[q * 4 + 3] = v.w;
    }
    __syncthreads();

    // layer-1 MLP: each half computes 32 of the 64 h outputs (16 fp16 pairs)
#pragma unroll 2
    for (int t = 0; t < 16; t++) {
        const int j = half * 32 + 2 * t;
        float acc0 = __ldg(&b1[j]);
        float acc1 = __ldg(&b1[j + 1]);
#pragma unroll
        for (int i = 0; i < 32; i++) {
            acc0 = fmaf(attr[i], W1_s[i * 64 + j],     acc0);
            acc1 = fmaf(attr[i], W1_s[i * 64 + j + 1], acc1);
        }
        const __half2 h2 = __halves2half2(
            __float2half_rn(fmaxf(acc0, 0.0f)),
            __float2half_rn(fmaxf(acc1, 0.0f)));
        Hu[e * 33 + half * 16 + t] = *(const unsigned*)&h2;
    }
    __syncthreads();   // H done; W1 alias may now be overwritten

    // ---- kick off cp.async pipeline ----
    prefetch_chunk(wst_b,        b2st,      b2, 0, tid); cp_commit();
    prefetch_chunk(wst_b + 8192, b2st + 64, b2, 1, tid); cp_commit();

    // ---- A fragments (chunk-invariant): 4 k-steps x 4 regs fp16x2 ----
    const int lane = tid & 31;
    const int warp = tid >> 5;          // 0..7 -> edges warp*16 .. +15
    const int gid  = lane >> 2;
    const int qd   = lane & 3;
    const int er0  = warp * 16 + gid;
    const int er1  = er0 + 8;

    unsigned a[4][4];
#pragma unroll
    for (int ks = 0; ks < 4; ks++) {
        a[ks][0] = Hu[er0 * 33 + 8 * ks + qd];
        a[ks][1] = Hu[er1 * 33 + 8 * ks + qd];
        a[ks][2] = Hu[er0 * 33 + 8 * ks + 4 + qd];
        a[ks][3] = Hu[er1 * 33 + 8 * ks + 4 + qd];
    }

    // ldmatrix per-thread offsets (within a chunk's 8-row n-block):
    //   lane l supplies row (l&7) of matrix (l>>3); stored seg = kseg ^ (row&7)
    const int lrow = lane & 7;
    const int lmat = lane >> 3;
    const unsigned lmoff0 = (unsigned)(lrow * 128 + (((lmat)     ^ lrow) << 4));
    const unsigned lmoff1 = (unsigned)(lrow * 128 + (((lmat | 4) ^ lrow) << 4));

    // accumulators
    float acc0[2][4][2];
    float cacc[2][2][2];
    float dacc[2][2][2][3];
#pragma unroll
    for (int r = 0; r < 2; r++) {
#pragma unroll
        for (int n = 0; n < 4; n++) { acc0[r][n][0] = 0.f; acc0[r][n][1] = 0.f; }
#pragma unroll
        for (int p = 0; p < 2; p++) {
            cacc[r][p][0] = 0.f; cacc[r][p][1] = 0.f;
#pragma unroll
            for (int j = 0; j < 2; j++) {
                dacc[r][p][j][0] = 0.f; dacc[r][p][j][1] = 0.f; dacc[r][p][j][2] = 0.f;
            }
        }
    }

    // ---- main pipelined loop over 36 column chunks of 64 ----
#pragma unroll 1
    for (int ch = 0; ch < 36; ch++) {
        cp_wait<1>();          // chunk ch resident (own thread's view)
        __syncthreads();       // visible to all; buffer (ch+2)%3 free
        if (ch + 2 < 36)
            prefetch_chunk(wst_b + ((ch + 2) % 3) * 8192,
                           b2st + ((ch + 2) % 3) * 64,
                           b2, ch + 2, tid);
        cp_commit();           // always commit to keep group count

        const unsigned chunk_b = wst_b + (unsigned)((ch % 3) * 8192);
        const float*   bb      = b2st + (ch % 3) * 64;

#pragma unroll
        for (int h2 = 0; h2 < 2; h2++) {
            // w half-chunk: c[n][{r0c0,r0c1,r1c0,r1c1}], bias-initialized
            float c[4][4];
#pragma unroll
            for (int n = 0; n < 4; n++) {
                const float bb0 = bb[(h2 * 4 + n) * 8 + 2 * qd];
                const float bb1 = bb[(h2 * 4 + n) * 8 + 2 * qd + 1];
                c[n][0] = bb0; c[n][1] = bb1; c[n][2] = bb0; c[n][3] = bb1;
            }
#pragma unroll
            for (int n = 0; n < 4; n++) {
                const unsigned nb_base = chunk_b + (unsigned)((h2 * 4 + n) * 1024);
                unsigned b0, b1, b2r, b3, b4, b5, b6, b7;
                ldsm_x4(b0, b1, b2r, b3, nb_base + lmoff0);   // ksegs 0..3
                ldsm_x4(b4, b5, b6,  b7, nb_base + lmoff1);   // ksegs 4..7
                mma_f16(c[n], a[0], b0, b1);
                mma_f16(c[n], a[1], b2r, b3);
                mma_f16(c[n], a[2], b4, b5);
                mma_f16(c[n], a[3], b6, b7);
            }

            // region-aware contraction
            if (ch < 16) {                      // A (wa): u = 2ch + h2
#pragma unroll
                for (int r = 0; r < 2; r++) {
                    const int er = r ? er1 : er0;
                    const float y = x0_s[er * 33 + 2 * ch + h2] * sh0_s[er];
#pragma unroll
                    for (int n = 0; n < 4; n++) {
                        acc0[r][n][0] = fmaf(c[n][r * 2 + 0], y, acc0[r][n][0]);
                        acc0[r][n][1] = fmaf(c[n][r * 2 + 1], y, acc0[r][n][1]);
                    }
                }
            } else if (ch < 24) {               // C (wc): u = 4ch' + 2h2 + {0,1}
                const int chp = ch - 16;
#pragma unroll
                for (int r = 0; r < 2; r++) {
                    const int er = r ? er1 : er0;
                    const float xa = x0_s[er * 33 + 4 * chp + h2 * 2 + 0];
                    const float xb = x0_s[er * 33 + 4 * chp + h2 * 2 + 1];
#pragma unroll
                    for (int p = 0; p < 2; p++) {
                        cacc[r][p][0] = fmaf(c[p][r * 2 + 0], xa,
                                        fmaf(c[2 + p][r * 2 + 0], xb, cacc[r][p][0]));
                        cacc[r][p][1] = fmaf(c[p][r * 2 + 1], xa,
                                        fmaf(c[2 + p][r * 2 + 1], xb, cacc[r][p][1]));
                    }
                }
            } else if (ch < 28) {               // D (wd): u = 4ch' + 2h2 + t
                const int chp = ch - 24;
#pragma unroll
                for (int r = 0; r < 2; r++) {
                    const int er = r ? er1 : er0;
#pragma unroll
                    for (int t = 0; t < 2; t++) {
                        const int u = 4 * chp + h2 * 2 + t;
                        const float za = z1_s[er * 49 + u * 3 + 0];
                        const float zb = z1_s[er * 49 + u * 3 + 1];
                        const float zc = z1_s[er * 49 + u * 3 + 2];
#pragma unroll
                        for (int p = 0; p < 2; p++) {
                            const int n = t * 2 + p;
#pragma unroll
                            for (int j = 0; j < 2; j++) {
                                const float wv = c[n][r * 2 + j];
                                dacc[r][p][j][0] = fmaf(wv, za, dacc[r][p][j][0]);
                                dacc[r][p][j][1] = fmaf(wv, zb, dacc[r][p][j][1]);
                                dacc[r][p][j][2] = fmaf(wv, zc, dacc[r][p][j][2]);
                            }
                        }
                    }
                }
            } else {                            // B (wb): u = 2ch' + h2
                const int chp = ch - 28;
#pragma unroll
                for (int r = 0; r < 2; r++) {
                    const int er = r ? er1 : er0;
                    const float y = y1_s[er * 17 + 2 * chp + h2];
#pragma unroll
                    for (int n = 0; n < 4; n++) {
                        acc0[r][n][0] = fmaf(c[n][r * 2 + 0], y, acc0[r][n][0]);
                        acc0[r][n][1] = fmaf(c[n][r * 2 + 1], y, acc0[r][n][1]);
                    }
                }
            }
        }
    }

    // ---- writeouts ----
#pragma unroll
    for (int r = 0; r < 2; r++) {
        const int er = r ? er1 : er0;
        if (eBase + er < E) {
            const int node = dst_s[er];
            const float s1v = sh1_s[er * 3 + 0];
            const float s2v = sh1_s[er * 3 + 1];
            const float s3v = sh1_s[er * 3 + 2];
            // out1 (cols 32..79): v = p*8 + 2qd + j
#pragma unroll
            for (int p = 0; p < 2; p++)
#pragma unroll
                for (int j = 0; j < 2; j++) {
                    const int v = p * 8 + 2 * qd + j;
                    const float cc = cacc[r][p][j];
                    atomicAdd(&g_sums[node * 80 + 32 + v * 3 + 0],
                              NORM_V * (s1v * cc + dacc[r][p][j][0]));
                    atomicAdd(&g_sums[node * 80 + 32 + v * 3 + 1],
                              NORM_V * (s2v * cc + dacc[r][p][j][1]));
                    atomicAdd(&g_sums[node * 80 + 32 + v * 3 + 2],
                              NORM_V * (s3v * cc + dacc[r][p][j][2]));
                }
            // out0 (cols 0..31)
#pragma unroll
            for (int n = 0; n < 4; n++) {
                const int col = n * 8 + 2 * qd;
                atomicAdd(&g_sums[node * 80 + col],     NORM_V * acc0[r][n][0]);
                atomicAdd(&g_sums[node * 80 + col + 1], NORM_V * acc0[r][n][1]);
            }
            if (qd == 0) atomicAdd(&g_cnt[node], 1.0f);
        }
    }
}

// ---------------------------------------------------------------------------
// residual + mean; restores g_sums/g_cnt to zero (graph-replay safe).
// 320 threads = 4 nodes/block; rw0/rw1 staged in smem.
// ---------------------------------------------------------------------------
__global__ __launch_bounds__(320) void final_kernel(
    int n_nodes,
    const float* __restrict__ x_dst,
    const float* __restrict__ rw0,
    const float* __restrict__ rw1,
    float* __restrict__ out)
{
    __shared__ float w0s[1024];
    __shared__ float w1s[256];
    __shared__ float cs[4];
    const int tid = threadIdx.x;

    for (int i = tid; i < 1024; i += 320) w0s[i] = rw0[i];
    if (tid < 256) w1s[tid] = rw1[tid];

    const int local = tid / 80;
    const int j     = tid - local * 80;
    const int n     = blockIdx.x * 4 + local;
    const bool ok   = (n < n_nodes);

    if (ok && j == 0) cs[local] = g_cnt[n];
    __syncthreads();
    if (!ok) return;

    float res;
    if (j < 32) {
        float acc = 0.f;
#pragma unroll
        for (int u = 0; u < 32; u++)
            acc = fmaf(x_dst[n * 80 + u], w0s[u * 32 + j], acc);
        res = acc * RSQRT32_V;
    } else {
        const int w = (j - 32) / 3;
        const int m = (j - 32) - 3 * w;
        float acc = 0.f;
#pragma unroll
        for (int u = 0; u < 16; u++)
            acc = fmaf(x_dst[n * 80 + 32 + u * 3 + m], w1s[u * 16 + w], acc);
        res = acc * 0.25f;
    }
    const int idx = n * 80 + j;
    const float c = fmaxf(cs[local], 1.0f);
    out[idx] = res + g_sums[idx] / c;

    // restore zeros for next replay
    g_sums[idx] = 0.0f;
    if (j == 0) g_cnt[n] = 0.0f;
}

// ---------------------------------------------------------------------------
extern "C" void kernel_launch(void* const* d_in, const int* in_sizes, int n_in,
                              void* d_out, int out_size)
{
    const int*   dst       = (const int*)  d_in[0];
    const float* x_src     = (const float*)d_in[1];
    const float* x_dst     = (const float*)d_in[2];
    const float* sh        = (const float*)d_in[3];
    const float* edge_attr = (const float*)d_in[4];
    const float* w1        = (const float*)d_in[5];
    const float* b1        = (const float*)d_in[6];
    const float* w2        = (const float*)d_in[7];
    const float* b2        = (const float*)d_in[8];
    const float* rw0       = (const float*)d_in[9];
    const float* rw1       = (const float*)d_in[10];
    float* out = (float*)d_out;

    const int E       = in_sizes[0];
    const int n_nodes = in_sizes[2] / OUT_DIM;

    cudaFuncSetAttribute(edge_kernel,
                         cudaFuncAttributeMaxDynamicSharedMemorySize,
                         SMEM_BYTES);

    dim3 cblk(32, 8);
    convert_w2<<<2304 / 32, cblk>>>(w2);
    edge_kernel<<<(E + 127) / 128, 256, SMEM_BYTES>>>(
        E, dst, x_src, sh, edge_attr, w1, b1, b2);
    final_kernel<<<(n_nodes + 3) / 4, 320>>>(
        n_nodes, x_dst, rw0, rw1, out);
}

// round 8
// speedup vs baseline: 1.9240x; 1.1087x over previous
#include <cuda_runtime.h>
#include <cuda_fp16.h>

// ---------------------------------------------------------------------------
// Conv_2259152798130 — fused e3nn edge conv.
// R8: both MLPs on tensor cores. MLP1 (attr@W1) via mma whose D fragments are
// bit-compatible with the main GEMM's A fragments (no H smem round-trip).
// Main GEMM fp16 m16n8k16 + cp.async pipeline + ldmatrix B fragments (R7).
//   region-aware contraction -> msg[E,80] -> atomic segment sum
//   out = residual + segment_mean  (final_kernel re-zeroes scratch)
// ---------------------------------------------------------------------------

#define NN       10000
#define OUT_DIM  80
#define NORM_V        0.14433756729740643f   // 1/sqrt(48)
#define INV_SQRT3_V   0.57735026918962576f
#define RSQRT32_V     0.17677669529663687f   // 1/sqrt(32)

// zero-initialized at module load; final_kernel restores zeros each run
__device__ float g_sums[NN * OUT_DIM];
__device__ float g_cnt[NN];
// W2 fp16: row j (out col) holds 64 k's as 32 half2 (128B rows)
__device__ unsigned g_w2h[2304 * 32];
// W1 fp16: row n (h col, 64 rows) holds 32 k's as 16 half2, padded to 32 (128B)
__device__ unsigned g_w1h[64 * 32];

// tiled transpose+convert for W2; block 72 converts W1
__global__ void convert_w2(const float* __restrict__ w2,
                           const float* __restrict__ w1) {
    __shared__ float s[64][33];
    const int x  = threadIdx.x;            // 0..31
    const int y  = threadIdx.y;            // 0..7
    if (blockIdx.x == 72) {                // W1: [k=32][n=64] -> padded rows
        const int lin = y * 32 + x;
        for (int i = lin; i < 2048; i += 256) {
            const int n = i >> 5;
            const int p = i & 31;
            unsigned v = 0u;
            if (p < 16) {
                const __half2 h2 = __halves2half2(
                    __float2half_rn(w1[(2 * p)     * 64 + n]),
                    __float2half_rn(w1[(2 * p + 1) * 64 + n]));
                v = *(const unsigned*)&h2;
            }
            g_w1h[i] = v;
        }
        return;
    }
    const int j0 = blockIdx.x * 32;
#pragma unroll
    for (int r = 0; r < 8; r++) {
        const int k = y * 8 + r;
        s[k][x] = w2[k * 2304 + j0 + x];
    }
    __syncthreads();
#pragma unroll
    for (int q = 0; q < 4; q++) {
        const int jj = y * 4 + q;
        const __half2 h2 = __halves2half2(
            __float2half_rn(s[2 * x][jj]),
            __float2half_rn(s[2 * x + 1][jj]));
        g_w2h[(j0 + jj) * 32 + x] = *(const unsigned*)&h2;
    }
}

// mma m16n8k16 fp16 -> fp32 accum (A row-major, B col-major)
__device__ __forceinline__ void mma_f16(float c[4], const unsigned a[4],
                                        unsigned b0, unsigned b1) {
    asm volatile(
        "mma.sync.aligned.m16n8k16.row.col.f32.f16.f16.f32 "
        "{%0,%1,%2,%3}, {%4,%5,%6,%7}, {%8,%9}, {%0,%1,%2,%3};"
        : "+f"(c[0]), "+f"(c[1]), "+f"(c[2]), "+f"(c[3])
        : "r"(a[0]), "r"(a[1]), "r"(a[2]), "r"(a[3]), "r"(b0), "r"(b1));
}

__device__ __forceinline__ void ldsm_x4(unsigned& r0, unsigned& r1,
                                        unsigned& r2, unsigned& r3,
                                        unsigned addr) {
    asm volatile("ldmatrix.sync.aligned.m8n8.x4.shared.b16 {%0,%1,%2,%3}, [%4];"
                 : "=r"(r0), "=r"(r1), "=r"(r2), "=r"(r3) : "r"(addr));
}

__device__ __forceinline__ void cp_commit() {
    asm volatile("cp.async.commit_group;" ::: "memory");
}
template <int N>
__device__ __forceinline__ void cp_wait() {
    asm volatile("cp.async.wait_group %0;" :: "n"(N) : "memory");
}

// prefetch one W2 chunk: 64 rows x 128B, seg ^= (n&7) swizzle, + 64 b2 floats
__device__ __forceinline__ void prefetch_chunk(
    unsigned wbuf_b, float* bbuf, const float* __restrict__ b2,
    int ch, int tid)
{
#pragma unroll
    for (int t = 0; t < 2; t++) {
        const int i = tid + t * 256;       // 0..511
        const int n = i >> 3;              // row (out col) 0..63
        const int s = i & 7;               // 16B segment within row
        const unsigned dst = wbuf_b + (unsigned)(n * 128 + ((s ^ (n & 7)) << 4));
        const char* src = (const char*)g_w2h + (size_t)(ch * 64 + n) * 128 + s * 16;
        asm volatile("cp.async.cg.shared.global [%0], [%1], 16;"
                     :: "r"(dst), "l"(src));
    }
    if (tid < 16) {
        unsigned dst;
        asm("{ .reg .u64 t; cvta.to.shared.u64 t, %1; cvt.u32.u64 %0, t; }"
            : "=r"(dst) : "l"(bbuf + tid * 4));
        const float* src = b2 + ch * 64 + tid * 4;
        asm volatile("cp.async.cg.shared.global [%0], [%1], 16;"
                     :: "r"(dst), "l"(src));
    }
}

// prefetch W1 fp16 (64 rows x 128B, same swizzle)
__device__ __forceinline__ void prefetch_w1(unsigned wbuf_b, int tid)
{
#pragma unroll
    for (int t = 0; t < 2; t++) {
        const int i = tid + t * 256;
        const int n = i >> 3;
        const int s = i & 7;
        const unsigned dst = wbuf_b + (unsigned)(n * 128 + ((s ^ (n & 7)) << 4));
        const char* src = (const char*)g_w1h + (size_t)n * 128 + s * 16;
        asm volatile("cp.async.cg.shared.global [%0], [%1], 16;"
                     :: "r"(dst), "l"(src));
    }
}

// ---------------------------------------------------------------------------
// Shared layout (4-byte units), 128 edges/block, total 21888 = 87552 B
//   attrh [128][17] u32 @ 0      (attr fp16 pairs)
//   b1s   [64]          @ 2176
//   Wst   [3][2048] u32 @ 2240   (fp16 stages; buf0 = W1 during MLP1)
//   b2st  [3][64]       @ 8384
//   x0_s  [128][33]     @ 8576
//   y1_s  [128][17]     @ 12800
//   z1_s  [128][49]     @ 14976
//   sh0_s [128]         @ 21248
//   sh1_s [128][3]      @ 21376
//   dst_s [128] int     @ 21760
// ---------------------------------------------------------------------------
#define SMEM_BYTES (21888 * 4)

__global__ __launch_bounds__(256, 2) void edge_kernel(
    int E,
    const int*   __restrict__ dst,
    const float* __restrict__ x_src,
    const float* __restrict__ sh,
    const float* __restrict__ edge_attr,
    const float* __restrict__ b1,
    const float* __restrict__ b2)
{
    extern __shared__ float smem[];
    unsigned* attrh = (unsigned*)smem;
    float* b1s   = smem + 2176;
    float* b2st  = smem + 8384;
    float* x0_s  = smem + 8576;
    float* y1_s  = smem + 12800;
    float* z1_s  = smem + 14976;
    float* sh0_s = smem + 21248;
    float* sh1_s = smem + 21376;
    int*   dst_s = (int*)(smem + 21760);

    unsigned wst_b;                        // byte smem addr of Wst
    asm("{ .reg .u64 t; cvta.to.shared.u64 t, %1; cvt.u32.u64 %0, t; }"
        : "=r"(wst_b) : "l"(smem + 2240));

    const int tid   = threadIdx.x;
    const int eBase = blockIdx.x * 128;
    const int e     = tid & 127;
    const int half  = tid >> 7;
    const int ge    = eBase + e;
    const bool valid = (ge < E);

    // ---- kick off cp.async: W1 -> buf0, chunk0 -> buf1, chunk1 -> buf2 ----
    prefetch_w1(wst_b, tid);                                    cp_commit();
    prefetch_chunk(wst_b + 8192,  b2st + 64,  b2, 0, tid);      cp_commit();
    prefetch_chunk(wst_b + 16384, b2st + 128, b2, 1, tid);      cp_commit();

    // ---- Phase 0: per-edge features + attr fp16 ----
    if (tid < 64) b1s[tid] = b1[tid];

    {   // attr: thread (e, half) converts 16 of 32 attrs
        const float* ap = edge_attr + (size_t)ge * 32 + half * 16;
#pragma unroll
        for (int q = 0; q < 4; q++) {
            float4 v = valid ? ((const float4*)ap)[q]
                             : make_float4(0.f, 0.f, 0.f, 0.f);
            __half2 p0 = __halves2half2(__float2half_rn(v.x), __float2half_rn(v.y));
            __half2 p1 = __halves2half2(__float2half_rn(v.z), __float2half_rn(v.w));
            attrh[e * 17 + half * 8 + q * 2]     = *(const unsigned*)&p0;
            attrh[e * 17 + half * 8 + q * 2 + 1] = *(const unsigned*)&p1;
        }
    }

    if (half == 0) {   // one thread per edge
        dst_s[e] = valid ? dst[ge] : 0;
        float s0 = 0.f, s1 = 0.f, s2 = 0.f, s3 = 0.f;
        if (valid) {
            const float4 shv = *(const float4*)&sh[ge * 4];
            s0 = shv.x; s1 = shv.y; s2 = shv.z; s3 = shv.w;
        }
        sh0_s[e] = s0;
        sh1_s[e * 3 + 0] = s1; sh1_s[e * 3 + 1] = s2; sh1_s[e * 3 + 2] = s3;
#pragma unroll
        for (int q = 0; q < 8; q++) {
            float4 v = valid ? ((const float4*)&x_src[ge * 80])[q]
                             : make_float4(0.f, 0.f, 0.f, 0.f);
            x0_s[e * 33 + q * 4 + 0] = v.x;
            x0_s[e * 33 + q * 4 + 1] = v.y;
            x0_s[e * 33 + q * 4 + 2] = v.z;
            x0_s[e * 33 + q * 4 + 3] = v.w;
        }
#pragma unroll
        for (int u = 0; u < 16; u++) {
            float a = 0.f, b = 0.f, c = 0.f;
            if (valid) {
                a = x_src[ge * 80 + 32 + u * 3 + 0];
                b = x_src[ge * 80 + 32 + u * 3 + 1];
                c = x_src[ge * 80 + 32 + u * 3 + 2];
            }
            y1_s[e * 17 + u] = INV_SQRT3_V * (a * s1 + b * s2 + c * s3);
            z1_s[e * 49 + u * 3 + 0] = a * s0;
            z1_s[e * 49 + u * 3 + 1] = b * s0;
            z1_s[e * 49 + u * 3 + 2] = c * s0;
        }
    }

    // W1 must be resident (chunk0/1 may still be in flight)
    cp_wait<2>();
    __syncthreads();

    // ---- warp identity ----
    const int lane = tid & 31;
    const int warp = tid >> 5;          // 0..7 -> edges warp*16 .. +15
    const int gid  = lane >> 2;
    const int qd   = lane & 3;
    const int er0  = warp * 16 + gid;
    const int er1  = er0 + 8;

    const int lrow = lane & 7;
    const int lmat = lane >> 3;
    const unsigned lmoff0 = (unsigned)(lrow * 128 + (((lmat)     ^ lrow) << 4));
    const unsigned lmoff1 = (unsigned)(lrow * 128 + (((lmat | 4) ^ lrow) << 4));

    // ---- MLP1 via mma: h fragments land directly in main-GEMM A regs ----
    unsigned a[4][4];
    {
        unsigned am[2][4];
        am[0][0] = attrh[er0 * 17 + qd];
        am[0][1] = attrh[er1 * 17 + qd];
        am[0][2] = attrh[er0 * 17 + 4 + qd];
        am[0][3] = attrh[er1 * 17 + 4 + qd];
        am[1][0] = attrh[er0 * 17 + 8 + qd];
        am[1][1] = attrh[er1 * 17 + 8 + qd];
        am[1][2] = attrh[er0 * 17 + 12 + qd];
        am[1][3] = attrh[er1 * 17 + 12 + qd];

        const float bb0a = b1s[2 * qd];     // re-read per tile below instead
#pragma unroll
        for (int t = 0; t < 8; t++) {
            float c[4];
            const float bb0 = b1s[t * 8 + 2 * qd];
            const float bb1 = b1s[t * 8 + 2 * qd + 1];
            c[0] = bb0; c[1] = bb1; c[2] = bb0; c[3] = bb1;
            unsigned b0, b1r, b2r, b3;
            ldsm_x4(b0, b1r, b2r, b3, wst_b + (unsigned)(t * 1024) + lmoff0);
            mma_f16(c, am[0], b0, b1r);
            mma_f16(c, am[1], b2r, b3);
            const __half2 plo = __halves2half2(
                __float2half_rn(fmaxf(c[0], 0.f)), __float2half_rn(fmaxf(c[1], 0.f)));
            const __half2 phi = __halves2half2(
                __float2half_rn(fmaxf(c[2], 0.f)), __float2half_rn(fmaxf(c[3], 0.f)));
            a[t >> 1][(t & 1) * 2 + 0] = *(const unsigned*)&plo;
            a[t >> 1][(t & 1) * 2 + 1] = *(const unsigned*)&phi;
        }
        (void)bb0a;
    }

    // accumulators
    float acc0[2][4][2];
    float cacc[2][2][2];
    float dacc[2][2][2][3];
#pragma unroll
    for (int r = 0; r < 2; r++) {
#pragma unroll
        for (int n = 0; n < 4; n++) { acc0[r][n][0] = 0.f; acc0[r][n][1] = 0.f; }
#pragma unroll
        for (int p = 0; p < 2; p++) {
            cacc[r][p][0] = 0.f; cacc[r][p][1] = 0.f;
#pragma unroll
            for (int j = 0; j < 2; j++) {
                dacc[r][p][j][0] = 0.f; dacc[r][p][j][1] = 0.f; dacc[r][p][j][2] = 0.f;
            }
        }
    }

    // ---- main pipelined loop: chunk ch lives in buf (ch+1)%3 ----
#pragma unroll 1
    for (int ch = 0; ch < 36; ch++) {
        cp_wait<1>();          // chunk ch resident (own thread's view)
        __syncthreads();       // visible to all; buf ch%3 free (W1 dead at ch=0)
        if (ch + 2 < 36)
            prefetch_chunk(wst_b + (unsigned)((ch % 3) * 8192),
                           b2st + (ch % 3) * 64,
                           b2, ch + 2, tid);
        cp_commit();           // always commit to keep group cadence

        const unsigned chunk_b = wst_b + (unsigned)(((ch + 1) % 3) * 8192);
        const float*   bb      = b2st + ((ch + 1) % 3) * 64;

#pragma unroll
        for (int h2 = 0; h2 < 2; h2++) {
            float c[4][4];
#pragma unroll
            for (int n = 0; n < 4; n++) {
                const float bb0 = bb[(h2 * 4 + n) * 8 + 2 * qd];
                const float bb1 = bb[(h2 * 4 + n) * 8 + 2 * qd + 1];
                c[n][0] = bb0; c[n][1] = bb1; c[n][2] = bb0; c[n][3] = bb1;
            }
#pragma unroll
            for (int n = 0; n < 4; n++) {
                const unsigned nb_base = chunk_b + (unsigned)((h2 * 4 + n) * 1024);
                unsigned b0, b1r, b2r, b3, b4, b5, b6, b7;
                ldsm_x4(b0, b1r, b2r, b3, nb_base + lmoff0);   // ksegs 0..3
                ldsm_x4(b4, b5, b6,  b7, nb_base + lmoff1);    // ksegs 4..7
                mma_f16(c[n], a[0], b0, b1r);
                mma_f16(c[n], a[1], b2r, b3);
                mma_f16(c[n], a[2], b4, b5);
                mma_f16(c[n], a[3], b6, b7);
            }

            // region-aware contraction
            if (ch < 16) {                      // A (wa): u = 2ch + h2
#pragma unroll
                for (int r = 0; r < 2; r++) {
                    const int er = r ? er1 : er0;
                    const float y = x0_s[er * 33 + 2 * ch + h2] * sh0_s[er];
#pragma unroll
                    for (int n = 0; n < 4; n++) {
                        acc0[r][n][0] = fmaf(c[n][r * 2 + 0], y, acc0[r][n][0]);
                        acc0[r][n][1] = fmaf(c[n][r * 2 + 1], y, acc0[r][n][1]);
                    }
                }
            } else if (ch < 24) {               // C (wc): u = 4ch' + 2h2 + {0,1}
                const int chp = ch - 16;
#pragma unroll
                for (int r = 0; r < 2; r++) {
                    const int er = r ? er1 : er0;
                    const float xa = x0_s[er * 33 + 4 * chp + h2 * 2 + 0];
                    const float xb = x0_s[er * 33 + 4 * chp + h2 * 2 + 1];
#pragma unroll
                    for (int p = 0; p < 2; p++) {
                        cacc[r][p][0] = fmaf(c[p][r * 2 + 0], xa,
                                        fmaf(c[2 + p][r * 2 + 0], xb, cacc[r][p][0]));
                        cacc[r][p][1] = fmaf(c[p][r * 2 + 1], xa,
                                        fmaf(c[2 + p][r * 2 + 1], xb, cacc[r][p][1]));
                    }
                }
            } else if (ch < 28) {               // D (wd): u = 4ch' + 2h2 + t
                const int chp = ch - 24;
#pragma unroll
                for (int r = 0; r < 2; r++) {
                    const int er = r ? er1 : er0;
#pragma unroll
                    for (int t = 0; t < 2; t++) {
                        const int u = 4 * chp + h2 * 2 + t;
                        const float za = z1_s[er * 49 + u * 3 + 0];
                        const float zb = z1_s[er * 49 + u * 3 + 1];
                        const float zc = z1_s[er * 49 + u * 3 + 2];
#pragma unroll
                        for (int p = 0; p < 2; p++) {
                            const int n = t * 2 + p;
#pragma unroll
                            for (int j = 0; j < 2; j++) {
                                const float wv = c[n][r * 2 + j];
                                dacc[r][p][j][0] = fmaf(wv, za, dacc[r][p][j][0]);
                                dacc[r][p][j][1] = fmaf(wv, zb, dacc[r][p][j][1]);
                                dacc[r][p][j][2] = fmaf(wv, zc, dacc[r][p][j][2]);
                            }
                        }
                    }
                }
            } else {                            // B (wb): u = 2ch' + h2
                const int chp = ch - 28;
#pragma unroll
                for (int r = 0; r < 2; r++) {
                    const int er = r ? er1 : er0;
                    const float y = y1_s[er * 17 + 2 * chp + h2];
#pragma unroll
                    for (int n = 0; n < 4; n++) {
                        acc0[r][n][0] = fmaf(c[n][r * 2 + 0], y, acc0[r][n][0]);
                        acc0[r][n][1] = fmaf(c[n][r * 2 + 1], y, acc0[r][n][1]);
                    }
                }
            }
        }
    }

    // ---- writeouts ----
#pragma unroll
    for (int r = 0; r < 2; r++) {
        const int er = r ? er1 : er0;
        if (eBase + er < E) {
            const int node = dst_s[er];
            const float s1v = sh1_s[er * 3 + 0];
            const float s2v = sh1_s[er * 3 + 1];
            const float s3v = sh1_s[er * 3 + 2];
            // out1 (cols 32..79): v = p*8 + 2qd + j
#pragma unroll
            for (int p = 0; p < 2; p++)
#pragma unroll
                for (int j = 0; j < 2; j++) {
                    const int v = p * 8 + 2 * qd + j;
                    const float cc = cacc[r][p][j];
                    atomicAdd(&g_sums[node * 80 + 32 + v * 3 + 0],
                              NORM_V * (s1v * cc + dacc[r][p][j][0]));
                    atomicAdd(&g_sums[node * 80 + 32 + v * 3 + 1],
                              NORM_V * (s2v * cc + dacc[r][p][j][1]));
                    atomicAdd(&g_sums[node * 80 + 32 + v * 3 + 2],
                              NORM_V * (s3v * cc + dacc[r][p][j][2]));
                }
            // out0 (cols 0..31)
#pragma unroll
            for (int n = 0; n < 4; n++) {
                const int col = n * 8 + 2 * qd;
                atomicAdd(&g_sums[node * 80 + col],     NORM_V * acc0[r][n][0]);
                atomicAdd(&g_sums[node * 80 + col + 1], NORM_V * acc0[r][n][1]);
            }
            if (qd == 0) atomicAdd(&g_cnt[node], 1.0f);
        }
    }
}

// ---------------------------------------------------------------------------
// residual + mean; restores g_sums/g_cnt to zero (graph-replay safe).
// 320 threads = 4 nodes/block; rw0/rw1 staged in smem.
// ---------------------------------------------------------------------------
__global__ __launch_bounds__(320) void final_kernel(
    int n_nodes,
    const float* __restrict__ x_dst,
    const float* __restrict__ rw0,
    const float* __restrict__ rw1,
    float* __restrict__ out)
{
    __shared__ float w0s[1024];
    __shared__ float w1s[256];
    __shared__ float cs[4];
    const int tid = threadIdx.x;

    for (int i = tid; i < 1024; i += 320) w0s[i] = rw0[i];
    if (tid < 256) w1s[tid] = rw1[tid];

    const int local = tid / 80;
    const int j     = tid - local * 80;
    const int n     = blockIdx.x * 4 + local;
    const bool ok   = (n < n_nodes);

    if (ok && j == 0) cs[local] = g_cnt[n];
    __syncthreads();
    if (!ok) return;

    float res;
    if (j < 32) {
        float acc = 0.f;
#pragma unroll
        for (int u = 0; u < 32; u++)
            acc = fmaf(x_dst[n * 80 + u], w0s[u * 32 + j], acc);
        res = acc * RSQRT32_V;
    } else {
        const int w = (j - 32) / 3;
        const int m = (j - 32) - 3 * w;
        float acc = 0.f;
#pragma unroll
        for (int u = 0; u < 16; u++)
            acc = fmaf(x_dst[n * 80 + 32 + u * 3 + m], w1s[u * 16 + w], acc);
        res = acc * 0.25f;
    }
    const int idx = n * 80 + j;
    const float c = fmaxf(cs[local], 1.0f);
    out[idx] = res + g_sums[idx] / c;

    // restore zeros for next replay
    g_sums[idx] = 0.0f;
    if (j == 0) g_cnt[n] = 0.0f;
}

// ---------------------------------------------------------------------------
extern "C" void kernel_launch(void* const* d_in, const int* in_sizes, int n_in,
                              void* d_out, int out_size)
{
    const int*   dst       = (const int*)  d_in[0];
    const float* x_src     = (const float*)d_in[1];
    const float* x_dst     = (const float*)d_in[2];
    const float* sh        = (const float*)d_in[3];
    const float* edge_attr = (const float*)d_in[4];
    const float* w1        = (const float*)d_in[5];
    const float* b1        = (const float*)d_in[6];
    const float* w2        = (const float*)d_in[7];
    const float* b2        = (const float*)d_in[8];
    const float* rw0       = (const float*)d_in[9];
    const float* rw1       = (const float*)d_in[10];
    float* out = (float*)d_out;

    const int E       = in_sizes[0];
    const int n_nodes = in_sizes[2] / OUT_DIM;

    cudaFuncSetAttribute(edge_kernel,
                         cudaFuncAttributeMaxDynamicSharedMemorySize,
                         SMEM_BYTES);

    dim3 cblk(32, 8);
    convert_w2<<<73, cblk>>>(w2, w1);
    edge_kernel<<<(E + 127) / 128, 256, SMEM_BYTES>>>(
        E, dst, x_src, sh, edge_attr, b1, b2);
    final_kernel<<<(n_nodes + 3) / 4, 320>>>(
        n_nodes, x_dst, rw0, rw1, out);
}

// round 9
// speedup vs baseline: 1.9909x; 1.0348x over previous
#include <cuda_runtime.h>
#include <cuda_fp16.h>

// ---------------------------------------------------------------------------
// Conv_2259152798130 — fused e3nn edge conv.
// R9: R8 (all-tensor-core MLPs, cp.async pipeline, ldmatrix B) +
//   - red.global.add.v2.f32 packed atomics (out0 pairs, out1 triples)
//   - out1 writeout hoisted to ch==28 (overlaps region-B mma)
//   - convert_w2 parallelism fix; final_kernel per-node reciprocal
// ---------------------------------------------------------------------------

#define NN       10000
#define OUT_DIM  80
#define NORM_V        0.14433756729740643f   // 1/sqrt(48)
#define INV_SQRT3_V   0.57735026918962576f
#define RSQRT32_V     0.17677669529663687f   // 1/sqrt(32)

// zero-initialized at module load; final_kernel restores zeros each run
__device__ float g_sums[NN * OUT_DIM];
__device__ float g_cnt[NN];
// W2 fp16: row j (out col) holds 64 k's as 32 half2 (128B rows)
__device__ unsigned g_w2h[2304 * 32];
// W1 fp16: row n (h col, 64 rows) holds 32 k's as 16 half2, padded to 32 (128B)
__device__ unsigned g_w1h[64 * 32];

// blocks 0..143: 16-col W2 tiles; block 144: W1. blockDim (16,8).
__global__ void convert_w2(const float* __restrict__ w2,
                           const float* __restrict__ w1) {
    const int lin = threadIdx.y * 16 + threadIdx.x;   // 0..127
    if (blockIdx.x == 144) {                          // W1 -> padded fp16 rows
        for (int i = lin; i < 2048; i += 128) {
            const int n = i >> 5;
            const int p = i & 31;
            unsigned v = 0u;
            if (p < 16) {
                const __half2 h2 = __halves2half2(
                    __float2half_rn(w1[(2 * p)     * 64 + n]),
                    __float2half_rn(w1[(2 * p + 1) * 64 + n]));
                v = *(const unsigned*)&h2;
            }
            g_w1h[i] = v;
        }
        return;
    }
    __shared__ float s[64][17];
    const int x  = threadIdx.x;            // 0..15 (j within tile)
    const int y  = threadIdx.y;            // 0..7
    const int j0 = blockIdx.x * 16;
#pragma unroll
    for (int r = 0; r < 8; r++) {
        const int k = y * 8 + r;
        s[k][x] = w2[k * 2304 + j0 + x];
    }
    __syncthreads();
    const int kp = lin & 31;
    const int jj = lin >> 5;               // 0..3
#pragma unroll
    for (int q = 0; q < 4; q++) {
        const int j = jj * 4 + q;
        const __half2 h2 = __halves2half2(
            __float2half_rn(s[2 * kp][j]),
            __float2half_rn(s[2 * kp + 1][j]));
        g_w2h[(j0 + j) * 32 + kp] = *(const unsigned*)&h2;
    }
}

// mma m16n8k16 fp16 -> fp32 accum (A row-major, B col-major)
__device__ __forceinline__ void mma_f16(float c[4], const unsigned a[4],
                                        unsigned b0, unsigned b1) {
    asm volatile(
        "mma.sync.aligned.m16n8k16.row.col.f32.f16.f16.f32 "
        "{%0,%1,%2,%3}, {%4,%5,%6,%7}, {%8,%9}, {%0,%1,%2,%3};"
        : "+f"(c[0]), "+f"(c[1]), "+f"(c[2]), "+f"(c[3])
        : "r"(a[0]), "r"(a[1]), "r"(a[2]), "r"(a[3]), "r"(b0), "r"(b1));
}

__device__ __forceinline__ void ldsm_x4(unsigned& r0, unsigned& r1,
                                        unsigned& r2, unsigned& r3,
                                        unsigned addr) {
    asm volatile("ldmatrix.sync.aligned.m8n8.x4.shared.b16 {%0,%1,%2,%3}, [%4];"
                 : "=r"(r0), "=r"(r1), "=r"(r2), "=r"(r3) : "r"(addr));
}

// packed / scalar global reductions (no return) — sm_90+ vector f32 atomics
__device__ __forceinline__ void red_add2(float* a, float x, float y) {
    asm volatile("red.global.add.v2.f32 [%0], {%1, %2};"
                 :: "l"(a), "f"(x), "f"(y) : "memory");
}
__device__ __forceinline__ void red_add1(float* a, float x) {
    asm volatile("red.global.add.f32 [%0], %1;"
                 :: "l"(a), "f"(x) : "memory");
}

__device__ __forceinline__ void cp_commit() {
    asm volatile("cp.async.commit_group;" ::: "memory");
}
template <int N>
__device__ __forceinline__ void cp_wait() {
    asm volatile("cp.async.wait_group %0;" :: "n"(N) : "memory");
}

// prefetch one W2 chunk: 64 rows x 128B, seg ^= (n&7) swizzle, + 64 b2 floats
__device__ __forceinline__ void prefetch_chunk(
    unsigned wbuf_b, float* bbuf, const float* __restrict__ b2,
    int ch, int tid)
{
#pragma unroll
    for (int t = 0; t < 2; t++) {
        const int i = tid + t * 256;       // 0..511
        const int n = i >> 3;              // row (out col) 0..63
        const int s = i & 7;               // 16B segment within row
        const unsigned dst = wbuf_b + (unsigned)(n * 128 + ((s ^ (n & 7)) << 4));
        const char* src = (const char*)g_w2h + (size_t)(ch * 64 + n) * 128 + s * 16;
        asm volatile("cp.async.cg.shared.global [%0], [%1], 16;"
                     :: "r"(dst), "l"(src));
    }
    if (tid < 16) {
        unsigned dst;
        asm("{ .reg .u64 t; cvta.to.shared.u64 t, %1; cvt.u32.u64 %0, t; }"
            : "=r"(dst) : "l"(bbuf + tid * 4));
        const float* src = b2 + ch * 64 + tid * 4;
        asm volatile("cp.async.cg.shared.global [%0], [%1], 16;"
                     :: "r"(dst), "l"(src));
    }
}

// prefetch W1 fp16 (64 rows x 128B, same swizzle)
__device__ __forceinline__ void prefetch_w1(unsigned wbuf_b, int tid)
{
#pragma unroll
    for (int t = 0; t < 2; t++) {
        const int i = tid + t * 256;
        const int n = i >> 3;
        const int s = i & 7;
        const unsigned dst = wbuf_b + (unsigned)(n * 128 + ((s ^ (n & 7)) << 4));
        const char* src = (const char*)g_w1h + (size_t)n * 128 + s * 16;
        asm volatile("cp.async.cg.shared.global [%0], [%1], 16;"
                     :: "r"(dst), "l"(src));
    }
}

// ---------------------------------------------------------------------------
// Shared layout (4-byte units), 128 edges/block, total 21888 = 87552 B
//   attrh [128][17] u32 @ 0      (attr fp16 pairs)
//   b1s   [64]          @ 2176
//   Wst   [3][2048] u32 @ 2240   (fp16 stages; buf0 = W1 during MLP1)
//   b2st  [3][64]       @ 8384
//   x0_s  [128][33]     @ 8576
//   y1_s  [128][17]     @ 12800
//   z1_s  [128][49]     @ 14976
//   sh0_s [128]         @ 21248
//   sh1_s [128][3]      @ 21376
//   dst_s [128] int     @ 21760
// ---------------------------------------------------------------------------
#define SMEM_BYTES (21888 * 4)

__global__ __launch_bounds__(256, 2) void edge_kernel(
    int E,
    const int*   __restrict__ dst,
    const float* __restrict__ x_src,
    const float* __restrict__ sh,
    const float* __restrict__ edge_attr,
    const float* __restrict__ b1,
    const float* __restrict__ b2)
{
    extern __shared__ float smem[];
    unsigned* attrh = (unsigned*)smem;
    float* b1s   = smem + 2176;
    float* b2st  = smem + 8384;
    float* x0_s  = smem + 8576;
    float* y1_s  = smem + 12800;
    float* z1_s  = smem + 14976;
    float* sh0_s = smem + 21248;
    float* sh1_s = smem + 21376;
    int*   dst_s = (int*)(smem + 21760);

    unsigned wst_b;                        // byte smem addr of Wst
    asm("{ .reg .u64 t; cvta.to.shared.u64 t, %1; cvt.u32.u64 %0, t; }"
        : "=r"(wst_b) : "l"(smem + 2240));

    const int tid   = threadIdx.x;
    const int eBase = blockIdx.x * 128;
    const int e     = tid & 127;
    const int half  = tid >> 7;
    const int ge    = eBase + e;
    const bool valid = (ge < E);

    // ---- kick off cp.async: W1 -> buf0, chunk0 -> buf1, chunk1 -> buf2 ----
    prefetch_w1(wst_b, tid);                                    cp_commit();
    prefetch_chunk(wst_b + 8192,  b2st + 64,  b2, 0, tid);      cp_commit();
    prefetch_chunk(wst_b + 16384, b2st + 128, b2, 1, tid);      cp_commit();

    // ---- Phase 0: per-edge features + attr fp16 ----
    if (tid < 64) b1s[tid] = b1[tid];

    {   // attr: thread (e, half) converts 16 of 32 attrs
        const float* ap = edge_attr + (size_t)ge * 32 + half * 16;
#pragma unroll
        for (int q = 0; q < 4; q++) {
            float4 v = valid ? ((const float4*)ap)[q]
                             : make_float4(0.f, 0.f, 0.f, 0.f);
            __half2 p0 = __halves2half2(__float2half_rn(v.x), __float2half_rn(v.y));
            __half2 p1 = __halves2half2(__float2half_rn(v.z), __float2half_rn(v.w));
            attrh[e * 17 + half * 8 + q * 2]     = *(const unsigned*)&p0;
            attrh[e * 17 + half * 8 + q * 2 + 1] = *(const unsigned*)&p1;
        }
    }

    if (half == 0) {   // one thread per edge
        dst_s[e] = valid ? dst[ge] : 0;
        float s0 = 0.f, s1 = 0.f, s2 = 0.f, s3 = 0.f;
        if (valid) {
            const float4 shv = *(const float4*)&sh[ge * 4];
            s0 = shv.x; s1 = shv.y; s2 = shv.z; s3 = shv.w;
        }
        sh0_s[e] = s0;
        sh1_s[e * 3 + 0] = s1; sh1_s[e * 3 + 1] = s2; sh1_s[e * 3 + 2] = s3;
#pragma unroll
        for (int q = 0; q < 8; q++) {
            float4 v = valid ? ((const float4*)&x_src[ge * 80])[q]
                             : make_float4(0.f, 0.f, 0.f, 0.f);
            x0_s[e * 33 + q * 4 + 0] = v.x;
            x0_s[e * 33 + q * 4 + 1] = v.y;
            x0_s[e * 33 + q * 4 + 2] = v.z;
            x0_s[e * 33 + q * 4 + 3] = v.w;
        }
#pragma unroll
        for (int u = 0; u < 16; u++) {
            float a = 0.f, b = 0.f, c = 0.f;
            if (valid) {
                a = x_src[ge * 80 + 32 + u * 3 + 0];
                b = x_src[ge * 80 + 32 + u * 3 + 1];
                c = x_src[ge * 80 + 32 + u * 3 + 2];
            }
            y1_s[e * 17 + u] = INV_SQRT3_V * (a * s1 + b * s2 + c * s3);
            z1_s[e * 49 + u * 3 + 0] = a * s0;
            z1_s[e * 49 + u * 3 + 1] = b * s0;
            z1_s[e * 49 + u * 3 + 2] = c * s0;
        }
    }

    // W1 must be resident (chunk0/1 may still be in flight)
    cp_wait<2>();
    __syncthreads();

    // ---- warp identity ----
    const int lane = tid & 31;
    const int warp = tid >> 5;          // 0..7 -> edges warp*16 .. +15
    const int gid  = lane >> 2;
    const int qd   = lane & 3;
    const int er0  = warp * 16 + gid;
    const int er1  = er0 + 8;

    const int lrow = lane & 7;
    const int lmat = lane >> 3;
    const unsigned lmoff0 = (unsigned)(lrow * 128 + (((lmat)     ^ lrow) << 4));
    const unsigned lmoff1 = (unsigned)(lrow * 128 + (((lmat | 4) ^ lrow) << 4));

    // ---- MLP1 via mma: h fragments land directly in main-GEMM A regs ----
    unsigned a[4][4];
    {
        unsigned am[2][4];
        am[0][0] = attrh[er0 * 17 + qd];
        am[0][1] = attrh[er1 * 17 + qd];
        am[0][2] = attrh[er0 * 17 + 4 + qd];
        am[0][3] = attrh[er1 * 17 + 4 + qd];
        am[1][0] = attrh[er0 * 17 + 8 + qd];
        am[1][1] = attrh[er1 * 17 + 8 + qd];
        am[1][2] = attrh[er0 * 17 + 12 + qd];
        am[1][3] = attrh[er1 * 17 + 12 + qd];

#pragma unroll
        for (int t = 0; t < 8; t++) {
            float c[4];
            const float bb0 = b1s[t * 8 + 2 * qd];
            const float bb1 = b1s[t * 8 + 2 * qd + 1];
            c[0] = bb0; c[1] = bb1; c[2] = bb0; c[3] = bb1;
            unsigned b0, b1r, b2r, b3;
            ldsm_x4(b0, b1r, b2r, b3, wst_b + (unsigned)(t * 1024) + lmoff0);
            mma_f16(c, am[0], b0, b1r);
            mma_f16(c, am[1], b2r, b3);
            const __half2 plo = __halves2half2(
                __float2half_rn(fmaxf(c[0], 0.f)), __float2half_rn(fmaxf(c[1], 0.f)));
            const __half2 phi = __halves2half2(
                __float2half_rn(fmaxf(c[2], 0.f)), __float2half_rn(fmaxf(c[3], 0.f)));
            a[t >> 1][(t & 1) * 2 + 0] = *(const unsigned*)&plo;
            a[t >> 1][(t & 1) * 2 + 1] = *(const unsigned*)&phi;
        }
    }

    // accumulators
    float acc0[2][4][2];
    float cacc[2][2][2];
    float dacc[2][2][2][3];
#pragma unroll
    for (int r = 0; r < 2; r++) {
#pragma unroll
        for (int n = 0; n < 4; n++) { acc0[r][n][0] = 0.f; acc0[r][n][1] = 0.f; }
#pragma unroll
        for (int p = 0; p < 2; p++) {
            cacc[r][p][0] = 0.f; cacc[r][p][1] = 0.f;
#pragma unroll
            for (int j = 0; j < 2; j++) {
                dacc[r][p][j][0] = 0.f; dacc[r][p][j][1] = 0.f; dacc[r][p][j][2] = 0.f;
            }
        }
    }

    // ---- main pipelined loop: chunk ch lives in buf (ch+1)%3 ----
#pragma unroll 1
    for (int ch = 0; ch < 36; ch++) {
        cp_wait<1>();          // chunk ch resident (own thread's view)
        __syncthreads();       // visible to all; buf ch%3 free (W1 dead at ch=0)
        if (ch + 2 < 36)
            prefetch_chunk(wst_b + (unsigned)((ch % 3) * 8192),
                           b2st + (ch % 3) * 64,
                           b2, ch + 2, tid);
        cp_commit();           // always commit to keep group cadence

        // ---- hoisted out1 writeout: cacc/dacc final after region D (ch 27);
        //      overlaps the remaining 8 region-B chunks of mma work ----
        if (ch == 28) {
#pragma unroll
            for (int r = 0; r < 2; r++) {
                const int er = r ? er1 : er0;
                if (eBase + er < E) {
                    const int node = dst_s[er];
                    const float s1v = sh1_s[er * 3 + 0];
                    const float s2v = sh1_s[er * 3 + 1];
                    const float s3v = sh1_s[er * 3 + 2];
#pragma unroll
                    for (int p = 0; p < 2; p++) {
                        const int v0 = p * 8 + 2 * qd;          // j = 0 (even v)
                        float* base0 = &g_sums[node * 80 + 32 + v0 * 3];
                        {
                            const float cc = cacc[r][p][0];
                            red_add2(base0,
                                     NORM_V * (s1v * cc + dacc[r][p][0][0]),
                                     NORM_V * (s2v * cc + dacc[r][p][0][1]));
                            red_add1(base0 + 2,
                                     NORM_V * (s3v * cc + dacc[r][p][0][2]));
                        }
                        {                                        // j = 1 (odd v)
                            const float cc = cacc[r][p][1];
                            red_add1(base0 + 3,
                                     NORM_V * (s1v * cc + dacc[r][p][1][0]));
                            red_add2(base0 + 4,
                                     NORM_V * (s2v * cc + dacc[r][p][1][1]),
                                     NORM_V * (s3v * cc + dacc[r][p][1][2]));
                        }
                    }
                }
            }
        }

        const unsigned chunk_b = wst_b + (unsigned)(((ch + 1) % 3) * 8192);
        const float*   bb      = b2st + ((ch + 1) % 3) * 64;

#pragma unroll
        for (int h2 = 0; h2 < 2; h2++) {
            float c[4][4];
#pragma unroll
            for (int n = 0; n < 4; n++) {
                const float bb0 = bb[(h2 * 4 + n) * 8 + 2 * qd];
                const float bb1 = bb[(h2 * 4 + n) * 8 + 2 * qd + 1];
                c[n][0] = bb0; c[n][1] = bb1; c[n][2] = bb0; c[n][3] = bb1;
            }
#pragma unroll
            for (int n = 0; n < 4; n++) {
                const unsigned nb_base = chunk_b + (unsigned)((h2 * 4 + n) * 1024);
                unsigned b0, b1r, b2r, b3, b4, b5, b6, b7;
                ldsm_x4(b0, b1r, b2r, b3, nb_base + lmoff0);   // ksegs 0..3
                ldsm_x4(b4, b5, b6,  b7, nb_base + lmoff1);    // ksegs 4..7
                mma_f16(c[n], a[0], b0, b1r);
                mma_f16(c[n], a[1], b2r, b3);
                mma_f16(c[n], a[2], b4, b5);
                mma_f16(c[n], a[3], b6, b7);
            }

            // region-aware contraction
            if (ch < 16) {                      // A (wa): u = 2ch + h2
#pragma unroll
                for (int r = 0; r < 2; r++) {
                    const int er = r ? er1 : er0;
                    const float y = x0_s[er * 33 + 2 * ch + h2] * sh0_s[er];
#pragma unroll
                    for (int n = 0; n < 4; n++) {
                        acc0[r][n][0] = fmaf(c[n][r * 2 + 0], y, acc0[r][n][0]);
                        acc0[r][n][1] = fmaf(c[n][r * 2 + 1], y, acc0[r][n][1]);
                    }
                }
            } else if (ch < 24) {               // C (wc): u = 4ch' + 2h2 + {0,1}
                const int chp = ch - 16;
#pragma unroll
                for (int r = 0; r < 2; r++) {
                    const int er = r ? er1 : er0;
                    const float xa = x0_s[er * 33 + 4 * chp + h2 * 2 + 0];
                    const float xb = x0_s[er * 33 + 4 * chp + h2 * 2 + 1];
#pragma unroll
                    for (int p = 0; p < 2; p++) {
                        cacc[r][p][0] = fmaf(c[p][r * 2 + 0], xa,
                                        fmaf(c[2 + p][r * 2 + 0], xb, cacc[r][p][0]));
                        cacc[r][p][1] = fmaf(c[p][r * 2 + 1], xa,
                                        fmaf(c[2 + p][r * 2 + 1], xb, cacc[r][p][1]));
                    }
                }
            } else if (ch < 28) {               // D (wd): u = 4ch' + 2h2 + t
                const int chp = ch - 24;
#pragma unroll
                for (int r = 0; r < 2; r++) {
                    const int er = r ? er1 : er0;
#pragma unroll
                    for (int t = 0; t < 2; t++) {
                        const int u = 4 * chp + h2 * 2 + t;
                        const float za = z1_s[er * 49 + u * 3 + 0];
                        const float zb = z1_s[er * 49 + u * 3 + 1];
                        const float zc = z1_s[er * 49 + u * 3 + 2];
#pragma unroll
                        for (int p = 0; p < 2; p++) {
                            const int n = t * 2 + p;
#pragma unroll
                            for (int j = 0; j < 2; j++) {
                                const float wv = c[n][r * 2 + j];
                                dacc[r][p][j][0] = fmaf(wv, za, dacc[r][p][j][0]);
                                dacc[r][p][j][1] = fmaf(wv, zb, dacc[r][p][j][1]);
                                dacc[r][p][j][2] = fmaf(wv, zc, dacc[r][p][j][2]);
                            }
                        }
                    }
                }
            } else {                            // B (wb): u = 2ch' + h2
                const int chp = ch - 28;
#pragma unroll
                for (int r = 0; r < 2; r++) {
                    const int er = r ? er1 : er0;
                    const float y = y1_s[er * 17 + 2 * chp + h2];
#pragma unroll
                    for (int n = 0; n < 4; n++) {
                        acc0[r][n][0] = fmaf(c[n][r * 2 + 0], y, acc0[r][n][0]);
                        acc0[r][n][1] = fmaf(c[n][r * 2 + 1], y, acc0[r][n][1]);
                    }
                }
            }
        }
    }

    // ---- out0 writeout (cols 0..31, packed pairs) + count ----
#pragma unroll
    for (int r = 0; r < 2; r++) {
        const int er = r ? er1 : er0;
        if (eBase + er < E) {
            const int node = dst_s[er];
#pragma unroll
            for (int n = 0; n < 4; n++) {
                const int col = n * 8 + 2 * qd;       // even -> 8B aligned
                red_add2(&g_sums[node * 80 + col],
                         NORM_V * acc0[r][n][0], NORM_V * acc0[r][n][1]);
            }
            if (qd == 0) red_add1(&g_cnt[node], 1.0f);
        }
    }
}

// ---------------------------------------------------------------------------
// residual + mean; restores g_sums/g_cnt to zero (graph-replay safe).
// 320 threads = 4 nodes/block; rw0/rw1 staged in smem; one rcp per node.
// ---------------------------------------------------------------------------
__global__ __launch_bounds__(320) void final_kernel(
    int n_nodes,
    const float* __restrict__ x_dst,
    const float* __restrict__ rw0,
    const float* __restrict__ rw1,
    float* __restrict__ out)
{
    __shared__ float w0s[1024];
    __shared__ float w1s[256];
    __shared__ float cs[4];
    const int tid = threadIdx.x;

    for (int i = tid; i < 1024; i += 320) w0s[i] = rw0[i];
    if (tid < 256) w1s[tid] = rw1[tid];

    const int local = tid / 80;
    const int j     = tid - local * 80;
    const int n     = blockIdx.x * 4 + local;
    const bool ok   = (n < n_nodes);

    if (ok && j == 0) cs[local] = 1.0f / fmaxf(g_cnt[n], 1.0f);
    __syncthreads();
    if (!ok) return;

    float res;
    if (j < 32) {
        float acc = 0.f;
#pragma unroll
        for (int u = 0; u < 32; u++)
            acc = fmaf(x_dst[n * 80 + u], w0s[u * 32 + j], acc);
        res = acc * RSQRT32_V;
    } else {
        const int w = (j - 32) / 3;
        const int m = (j - 32) - 3 * w;
        float acc = 0.f;
#pragma unroll
        for (int u = 0; u < 16; u++)
            acc = fmaf(x_dst[n * 80 + 32 + u * 3 + m], w1s[u * 16 + w], acc);
        res = acc * 0.25f;
    }
    const int idx = n * 80 + j;
    out[idx] = fmaf(g_sums[idx], cs[local], res);

    // restore zeros for next replay
    g_sums[idx] = 0.0f;
    if (j == 0) g_cnt[n] = 0.0f;
}

// ---------------------------------------------------------------------------
extern "C" void kernel_launch(void* const* d_in, const int* in_sizes, int n_in,
                              void* d_out, int out_size)
{
    const int*   dst       = (const int*)  d_in[0];
    const float* x_src     = (const float*)d_in[1];
    const float* x_dst     = (const float*)d_in[2];
    const float* sh        = (const float*)d_in[3];
    const float* edge_attr = (const float*)d_in[4];
    const float* w1        = (const float*)d_in[5];
    const float* b1        = (const float*)d_in[6];
    const float* w2        = (const float*)d_in[7];
    const float* b2        = (const float*)d_in[8];
    const float* rw0       = (const float*)d_in[9];
    const float* rw1       = (const float*)d_in[10];
    float* out = (float*)d_out;

    const int E       = in_sizes[0];
    const int n_nodes = in_sizes[2] / OUT_DIM;

    cudaFuncSetAttribute(edge_kernel,
                         cudaFuncAttributeMaxDynamicSharedMemorySize,
                         SMEM_BYTES);

    dim3 cblk(16, 8);
    convert_w2<<<145, cblk>>>(w2, w1);
    edge_kernel<<<(E + 127) / 128, 256, SMEM_BYTES>>>(
        E, dst, x_src, sh, edge_attr, b1, b2);
    final_kernel<<<(n_nodes + 3) / 4, 320>>>(
        n_nodes, x_dst, rw0, rw1, out);
}

// round 10
// speedup vs baseline: 2.1371x; 1.0734x over previous
#include <cuda_runtime.h>
#include <cuda_fp16.h>

// ---------------------------------------------------------------------------
// Conv_2259152798130 — fused e3nn edge conv.
// R10: R9 (all-tensor-core MLPs, cp.async pipeline, ldmatrix B, packed REDs)
//   with 64-edge tiles / 128 threads / 4 CTAs/SM to halve the tail work
//   quantum (13.6% -> 4.2% quantization waste), and a high-parallelism
//   convert_w2 (one thread per packed half2, coalesced writes).
// ---------------------------------------------------------------------------

#define NN       10000
#define OUT_DIM  80
#define NORM_V        0.14433756729740643f   // 1/sqrt(48)
#define INV_SQRT3_V   0.57735026918962576f
#define RSQRT32_V     0.17677669529663687f   // 1/sqrt(32)

// zero-initialized at module load; final_kernel restores zeros each run
__device__ float g_sums[NN * OUT_DIM];
__device__ float g_cnt[NN];
// W2 fp16: row j (out col) holds 64 k's as 32 half2 (128B rows)
__device__ unsigned g_w2h[2304 * 32];
// W1 fp16: row n (h col, 64 rows) holds 32 k's as 16 half2, padded to 32 (128B)
__device__ unsigned g_w1h[64 * 32];

// one thread per packed half2 of g_w2h (73728); block 288 converts W1.
__global__ void convert_w2(const float* __restrict__ w2,
                           const float* __restrict__ w1) {
    const int tid = threadIdx.x;
    if (blockIdx.x == 288) {                          // W1 -> padded fp16 rows
        for (int i = tid; i < 2048; i += 256) {
            const int n = i >> 5;
            const int p = i & 31;
            unsigned v = 0u;
            if (p < 16) {
                const __half2 h2 = __halves2half2(
                    __float2half_rn(w1[(2 * p)     * 64 + n]),
                    __float2half_rn(w1[(2 * p + 1) * 64 + n]));
                v = *(const unsigned*)&h2;
            }
            g_w1h[i] = v;
        }
        return;
    }
    const int i  = blockIdx.x * 256 + tid;            // 0..73727
    const int kp = i & 31;
    const int j  = i >> 5;
    const __half2 h2 = __halves2half2(
        __float2half_rn(__ldg(&w2[(2 * kp)     * 2304 + j])),
        __float2half_rn(__ldg(&w2[(2 * kp + 1) * 2304 + j])));
    g_w2h[i] = *(const unsigned*)&h2;                 // coalesced (kp fast)
}

// mma m16n8k16 fp16 -> fp32 accum (A row-major, B col-major)
__device__ __forceinline__ void mma_f16(float c[4], const unsigned a[4],
                                        unsigned b0, unsigned b1) {
    asm volatile(
        "mma.sync.aligned.m16n8k16.row.col.f32.f16.f16.f32 "
        "{%0,%1,%2,%3}, {%4,%5,%6,%7}, {%8,%9}, {%0,%1,%2,%3};"
        : "+f"(c[0]), "+f"(c[1]), "+f"(c[2]), "+f"(c[3])
        : "r"(a[0]), "r"(a[1]), "r"(a[2]), "r"(a[3]), "r"(b0), "r"(b1));
}

__device__ __forceinline__ void ldsm_x4(unsigned& r0, unsigned& r1,
                                        unsigned& r2, unsigned& r3,
                                        unsigned addr) {
    asm volatile("ldmatrix.sync.aligned.m8n8.x4.shared.b16 {%0,%1,%2,%3}, [%4];"
                 : "=r"(r0), "=r"(r1), "=r"(r2), "=r"(r3) : "r"(addr));
}

// packed / scalar global reductions (no return)
__device__ __forceinline__ void red_add2(float* a, float x, float y) {
    asm volatile("red.global.add.v2.f32 [%0], {%1, %2};"
                 :: "l"(a), "f"(x), "f"(y) : "memory");
}
__device__ __forceinline__ void red_add1(float* a, float x) {
    asm volatile("red.global.add.f32 [%0], %1;"
                 :: "l"(a), "f"(x) : "memory");
}

__device__ __forceinline__ void cp_commit() {
    asm volatile("cp.async.commit_group;" ::: "memory");
}
template <int N>
__device__ __forceinline__ void cp_wait() {
    asm volatile("cp.async.wait_group %0;" :: "n"(N) : "memory");
}

// prefetch one W2 chunk: 64 rows x 128B, seg ^= (n&7) swizzle, + 64 b2 floats
// 512 x 16B segments over 128 threads (4 each)
__device__ __forceinline__ void prefetch_chunk(
    unsigned wbuf_b, float* bbuf, const float* __restrict__ b2,
    int ch, int tid)
{
#pragma unroll
    for (int t = 0; t < 4; t++) {
        const int i = tid + t * 128;       // 0..511
        const int n = i >> 3;              // row (out col) 0..63
        const int s = i & 7;               // 16B segment within row
        const unsigned dst = wbuf_b + (unsigned)(n * 128 + ((s ^ (n & 7)) << 4));
        const char* src = (const char*)g_w2h + (size_t)(ch * 64 + n) * 128 + s * 16;
        asm volatile("cp.async.cg.shared.global [%0], [%1], 16;"
                     :: "r"(dst), "l"(src));
    }
    if (tid < 16) {
        unsigned dst;
        asm("{ .reg .u64 t; cvta.to.shared.u64 t, %1; cvt.u32.u64 %0, t; }"
            : "=r"(dst) : "l"(bbuf + tid * 4));
        const float* src = b2 + ch * 64 + tid * 4;
        asm volatile("cp.async.cg.shared.global [%0], [%1], 16;"
                     :: "r"(dst), "l"(src));
    }
}

// prefetch W1 fp16 (64 rows x 128B, same swizzle), 4 segments per thread
__device__ __forceinline__ void prefetch_w1(unsigned wbuf_b, int tid)
{
#pragma unroll
    for (int t = 0; t < 4; t++) {
        const int i = tid + t * 128;
        const int n = i >> 3;
        const int s = i & 7;
        const unsigned dst = wbuf_b + (unsigned)(n * 128 + ((s ^ (n & 7)) << 4));
        const char* src = (const char*)g_w1h + (size_t)n * 128 + s * 16;
        asm volatile("cp.async.cg.shared.global [%0], [%1], 16;"
                     :: "r"(dst), "l"(src));
    }
}

// ---------------------------------------------------------------------------
// Shared layout (4-byte units), 64 edges/block, total 14144 = 56576 B
//   attrh [64][17] u32 @ 0      (attr fp16 pairs)
//   b1s   [64]         @ 1088
//   Wst   [3][2048]u32 @ 1152   (fp16 stages; buf0 = W1 during MLP1)
//   b2st  [3][64]      @ 7296
//   x0_s  [64][33]     @ 7488
//   y1_s  [64][17]     @ 9600
//   z1_s  [64][49]     @ 10688
//   sh0_s [64]         @ 13824
//   sh1_s [64][3]      @ 13888
//   dst_s [64] int     @ 14080
// ---------------------------------------------------------------------------
#define SMEM_BYTES (14144 * 4)

__global__ __launch_bounds__(128, 4) void edge_kernel(
    int E,
    const int*   __restrict__ dst,
    const float* __restrict__ x_src,
    const float* __restrict__ sh,
    const float* __restrict__ edge_attr,
    const float* __restrict__ b1,
    const float* __restrict__ b2)
{
    extern __shared__ float smem[];
    unsigned* attrh = (unsigned*)smem;
    float* b1s   = smem + 1088;
    float* b2st  = smem + 7296;
    float* x0_s  = smem + 7488;
    float* y1_s  = smem + 9600;
    float* z1_s  = smem + 10688;
    float* sh0_s = smem + 13824;
    float* sh1_s = smem + 13888;
    int*   dst_s = (int*)(smem + 14080);

    unsigned wst_b;                        // byte smem addr of Wst
    asm("{ .reg .u64 t; cvta.to.shared.u64 t, %1; cvt.u32.u64 %0, t; }"
        : "=r"(wst_b) : "l"(smem + 1152));

    const int tid   = threadIdx.x;
    const int eBase = blockIdx.x * 64;
    const int e     = tid & 63;
    const int half  = tid >> 6;
    const int ge    = eBase + e;
    const bool valid = (ge < E);

    // ---- kick off cp.async: W1 -> buf0, chunk0 -> buf1, chunk1 -> buf2 ----
    prefetch_w1(wst_b, tid);                                    cp_commit();
    prefetch_chunk(wst_b + 8192,  b2st + 64,  b2, 0, tid);      cp_commit();
    prefetch_chunk(wst_b + 16384, b2st + 128, b2, 1, tid);      cp_commit();

    // ---- Phase 0: per-edge features + attr fp16 ----
    if (tid < 64) b1s[tid] = b1[tid];

    {   // attr: thread (e, half) converts 16 of 32 attrs
        const float* ap = edge_attr + (size_t)ge * 32 + half * 16;
#pragma unroll
        for (int q = 0; q < 4; q++) {
            float4 v = valid ? ((const float4*)ap)[q]
                             : make_float4(0.f, 0.f, 0.f, 0.f);
            __half2 p0 = __halves2half2(__float2half_rn(v.x), __float2half_rn(v.y));
            __half2 p1 = __halves2half2(__float2half_rn(v.z), __float2half_rn(v.w));
            attrh[e * 17 + half * 8 + q * 2]     = *(const unsigned*)&p0;
            attrh[e * 17 + half * 8 + q * 2 + 1] = *(const unsigned*)&p1;
        }
    }

    if (half == 0) {   // one thread per edge
        dst_s[e] = valid ? dst[ge] : 0;
        float s0 = 0.f, s1 = 0.f, s2 = 0.f, s3 = 0.f;
        if (valid) {
            const float4 shv = *(const float4*)&sh[ge * 4];
            s0 = shv.x; s1 = shv.y; s2 = shv.z; s3 = shv.w;
        }
        sh0_s[e] = s0;
        sh1_s[e * 3 + 0] = s1; sh1_s[e * 3 + 1] = s2; sh1_s[e * 3 + 2] = s3;
#pragma unroll
        for (int q = 0; q < 8; q++) {
            float4 v = valid ? ((const float4*)&x_src[ge * 80])[q]
                             : make_float4(0.f, 0.f, 0.f, 0.f);
            x0_s[e * 33 + q * 4 + 0] = v.x;
            x0_s[e * 33 + q * 4 + 1] = v.y;
            x0_s[e * 33 + q * 4 + 2] = v.z;
            x0_s[e * 33 + q * 4 + 3] = v.w;
        }
#pragma unroll
        for (int u = 0; u < 16; u++) {
            float a = 0.f, b = 0.f, c = 0.f;
            if (valid) {
                a = x_src[ge * 80 + 32 + u * 3 + 0];
                b = x_src[ge * 80 + 32 + u * 3 + 1];
                c = x_src[ge * 80 + 32 + u * 3 + 2];
            }
            y1_s[e * 17 + u] = INV_SQRT3_V * (a * s1 + b * s2 + c * s3);
            z1_s[e * 49 + u * 3 + 0] = a * s0;
            z1_s[e * 49 + u * 3 + 1] = b * s0;
            z1_s[e * 49 + u * 3 + 2] = c * s0;
        }
    }

    // W1 must be resident (chunk0/1 may still be in flight)
    cp_wait<2>();
    __syncthreads();

    // ---- warp identity ----
    const int lane = tid & 31;
    const int warp = tid >> 5;          // 0..3 -> edges warp*16 .. +15
    const int gid  = lane >> 2;
    const int qd   = lane & 3;
    const int er0  = warp * 16 + gid;
    const int er1  = er0 + 8;

    const int lrow = lane & 7;
    const int lmat = lane >> 3;
    const unsigned lmoff0 = (unsigned)(lrow * 128 + (((lmat)     ^ lrow) << 4));
    const unsigned lmoff1 = (unsigned)(lrow * 128 + (((lmat | 4) ^ lrow) << 4));

    // ---- MLP1 via mma: h fragments land directly in main-GEMM A regs ----
    unsigned a[4][4];
    {
        unsigned am[2][4];
        am[0][0] = attrh[er0 * 17 + qd];
        am[0][1] = attrh[er1 * 17 + qd];
        am[0][2] = attrh[er0 * 17 + 4 + qd];
        am[0][3] = attrh[er1 * 17 + 4 + qd];
        am[1][0] = attrh[er0 * 17 + 8 + qd];
        am[1][1] = attrh[er1 * 17 + 8 + qd];
        am[1][2] = attrh[er0 * 17 + 12 + qd];
        am[1][3] = attrh[er1 * 17 + 12 + qd];

#pragma unroll
        for (int t = 0; t < 8; t++) {
            float c[4];
            const float bb0 = b1s[t * 8 + 2 * qd];
            const float bb1 = b1s[t * 8 + 2 * qd + 1];
            c[0] = bb0; c[1] = bb1; c[2] = bb0; c[3] = bb1;
            unsigned b0, b1r, b2r, b3;
            ldsm_x4(b0, b1r, b2r, b3, wst_b + (unsigned)(t * 1024) + lmoff0);
            mma_f16(c, am[0], b0, b1r);
            mma_f16(c, am[1], b2r, b3);
            const __half2 plo = __halves2half2(
                __float2half_rn(fmaxf(c[0], 0.f)), __float2half_rn(fmaxf(c[1], 0.f)));
            const __half2 phi = __halves2half2(
                __float2half_rn(fmaxf(c[2], 0.f)), __float2half_rn(fmaxf(c[3], 0.f)));
            a[t >> 1][(t & 1) * 2 + 0] = *(const unsigned*)&plo;
            a[t >> 1][(t & 1) * 2 + 1] = *(const unsigned*)&phi;
        }
    }

    // accumulators
    float acc0[2][4][2];
    float cacc[2][2][2];
    float dacc[2][2][2][3];
#pragma unroll
    for (int r = 0; r < 2; r++) {
#pragma unroll
        for (int n = 0; n < 4; n++) { acc0[r][n][0] = 0.f; acc0[r][n][1] = 0.f; }
#pragma unroll
        for (int p = 0; p < 2; p++) {
            cacc[r][p][0] = 0.f; cacc[r][p][1] = 0.f;
#pragma unroll
            for (int j = 0; j < 2; j++) {
                dacc[r][p][j][0] = 0.f; dacc[r][p][j][1] = 0.f; dacc[r][p][j][2] = 0.f;
            }
        }
    }

    // ---- main pipelined loop: chunk ch lives in buf (ch+1)%3 ----
#pragma unroll 1
    for (int ch = 0; ch < 36; ch++) {
        cp_wait<1>();          // chunk ch resident (own thread's view)
        __syncthreads();       // visible to all; buf ch%3 free (W1 dead at ch=0)
        if (ch + 2 < 36)
            prefetch_chunk(wst_b + (unsigned)((ch % 3) * 8192),
                           b2st + (ch % 3) * 64,
                           b2, ch + 2, tid);
        cp_commit();           // always commit to keep group cadence

        // ---- hoisted out1 writeout: cacc/dacc final after region D (ch 27);
        //      overlaps the remaining 8 region-B chunks of mma work ----
        if (ch == 28) {
#pragma unroll
            for (int r = 0; r < 2; r++) {
                const int er = r ? er1 : er0;
                if (eBase + er < E) {
                    const int node = dst_s[er];
                    const float s1v = sh1_s[er * 3 + 0];
                    const float s2v = sh1_s[er * 3 + 1];
                    const float s3v = sh1_s[er * 3 + 2];
#pragma unroll
                    for (int p = 0; p < 2; p++) {
                        const int v0 = p * 8 + 2 * qd;          // j = 0 (even v)
                        float* base0 = &g_sums[node * 80 + 32 + v0 * 3];
                        {
                            const float cc = cacc[r][p][0];
                            red_add2(base0,
                                     NORM_V * (s1v * cc + dacc[r][p][0][0]),
                                     NORM_V * (s2v * cc + dacc[r][p][0][1]));
                            red_add1(base0 + 2,
                                     NORM_V * (s3v * cc + dacc[r][p][0][2]));
                        }
                        {                                        // j = 1 (odd v)
                            const float cc = cacc[r][p][1];
                            red_add1(base0 + 3,
                                     NORM_V * (s1v * cc + dacc[r][p][1][0]));
                            red_add2(base0 + 4,
                                     NORM_V * (s2v * cc + dacc[r][p][1][1]),
                                     NORM_V * (s3v * cc + dacc[r][p][1][2]));
                        }
                    }
                }
            }
        }

        const unsigned chunk_b = wst_b + (unsigned)(((ch + 1) % 3) * 8192);
        const float*   bb      = b2st + ((ch + 1) % 3) * 64;

#pragma unroll
        for (int h2 = 0; h2 < 2; h2++) {
            float c[4][4];
#pragma unroll
            for (int n = 0; n < 4; n++) {
                const float bb0 = bb[(h2 * 4 + n) * 8 + 2 * qd];
                const float bb1 = bb[(h2 * 4 + n) * 8 + 2 * qd + 1];
                c[n][0] = bb0; c[n][1] = bb1; c[n][2] = bb0; c[n][3] = bb1;
            }
#pragma unroll
            for (int n = 0; n < 4; n++) {
                const unsigned nb_base = chunk_b + (unsigned)((h2 * 4 + n) * 1024);
                unsigned b0, b1r, b2r, b3, b4, b5, b6, b7;
                ldsm_x4(b0, b1r, b2r, b3, nb_base + lmoff0);   // ksegs 0..3
                ldsm_x4(b4, b5, b6,  b7, nb_base + lmoff1);    // ksegs 4..7
                mma_f16(c[n], a[0], b0, b1r);
                mma_f16(c[n], a[1], b2r, b3);
                mma_f16(c[n], a[2], b4, b5);
                mma_f16(c[n], a[3], b6, b7);
            }

            // region-aware contraction
            if (ch < 16) {                      // A (wa): u = 2ch + h2
#pragma unroll
                for (int r = 0; r < 2; r++) {
                    const int er = r ? er1 : er0;
                    const float y = x0_s[er * 33 + 2 * ch + h2] * sh0_s[er];
#pragma unroll
                    for (int n = 0; n < 4; n++) {
                        acc0[r][n][0] = fmaf(c[n][r * 2 + 0], y, acc0[r][n][0]);
                        acc0[r][n][1] = fmaf(c[n][r * 2 + 1], y, acc0[r][n][1]);
                    }
                }
            } else if (ch < 24) {               // C (wc): u = 4ch' + 2h2 + {0,1}
                const int chp = ch - 16;
#pragma unroll
                for (int r = 0; r < 2; r++) {
                    const int er = r ? er1 : er0;
                    const float xa = x0_s[er * 33 + 4 * chp + h2 * 2 + 0];
                    const float xb = x0_s[er * 33 + 4 * chp + h2 * 2 + 1];
#pragma unroll
                    for (int p = 0; p < 2; p++) {
                        cacc[r][p][0] = fmaf(c[p][r * 2 + 0], xa,
                                        fmaf(c[2 + p][r * 2 + 0], xb, cacc[r][p][0]));
                        cacc[r][p][1] = fmaf(c[p][r * 2 + 1], xa,
                                        fmaf(c[2 + p][r * 2 + 1], xb, cacc[r][p][1]));
                    }
                }
            } else if (ch < 28) {               // D (wd): u = 4ch' + 2h2 + t
                const int chp = ch - 24;
#pragma unroll
                for (int r = 0; r < 2; r++) {
                    const int er = r ? er1 : er0;
#pragma unroll
                    for (int t = 0; t < 2; t++) {
                        const int u = 4 * chp + h2 * 2 + t;
                        const float za = z1_s[er * 49 + u * 3 + 0];
                        const float zb = z1_s[er * 49 + u * 3 + 1];
                        const float zc = z1_s[er * 49 + u * 3 + 2];
#pragma unroll
                        for (int p = 0; p < 2; p++) {
                            const int n = t * 2 + p;
#pragma unroll
                            for (int j = 0; j < 2; j++) {
                                const float wv = c[n][r * 2 + j];
                                dacc[r][p][j][0] = fmaf(wv, za, dacc[r][p][j][0]);
                                dacc[r][p][j][1] = fmaf(wv, zb, dacc[r][p][j][1]);
                                dacc[r][p][j][2] = fmaf(wv, zc, dacc[r][p][j][2]);
                            }
                        }
                    }
                }
            } else {                            // B (wb): u = 2ch' + h2
                const int chp = ch - 28;
#pragma unroll
                for (int r = 0; r < 2; r++) {
                    const int er = r ? er1 : er0;
                    const float y = y1_s[er * 17 + 2 * chp + h2];
#pragma unroll
                    for (int n = 0; n < 4; n++) {
                        acc0[r][n][0] = fmaf(c[n][r * 2 + 0], y, acc0[r][n][0]);
                        acc0[r][n][1] = fmaf(c[n][r * 2 + 1], y, acc0[r][n][1]);
                    }
                }
            }
        }
    }

    // ---- out0 writeout (cols 0..31, packed pairs) + count ----
#pragma unroll
    for (int r = 0; r < 2; r++) {
        const int er = r ? er1 : er0;
        if (eBase + er < E) {
            const int node = dst_s[er];
#pragma unroll
            for (int n = 0; n < 4; n++) {
                const int col = n * 8 + 2 * qd;       // even -> 8B aligned
                red_add2(&g_sums[node * 80 + col],
                         NORM_V * acc0[r][n][0], NORM_V * acc0[r][n][1]);
            }
            if (qd == 0) red_add1(&g_cnt[node], 1.0f);
        }
    }
}

// ---------------------------------------------------------------------------
// residual + mean; restores g_sums/g_cnt to zero (graph-replay safe).
// 320 threads = 4 nodes/block; rw0/rw1 staged in smem; one rcp per node.
// ---------------------------------------------------------------------------
__global__ __launch_bounds__(320) void final_kernel(
    int n_nodes,
    const float* __restrict__ x_dst,
    const float* __restrict__ rw0,
    const float* __restrict__ rw1,
    float* __restrict__ out)
{
    __shared__ float w0s[1024];
    __shared__ float w1s[256];
    __shared__ float cs[4];
    const int tid = threadIdx.x;

    for (int i = tid; i < 1024; i += 320) w0s[i] = rw0[i];
    if (tid < 256) w1s[tid] = rw1[tid];

    const int local = tid / 80;
    const int j     = tid - local * 80;
    const int n     = blockIdx.x * 4 + local;
    const bool ok   = (n < n_nodes);

    if (ok && j == 0) cs[local] = 1.0f / fmaxf(g_cnt[n], 1.0f);
    __syncthreads();
    if (!ok) return;

    float res;
    if (j < 32) {
        float acc = 0.f;
#pragma unroll
        for (int u = 0; u < 32; u++)
            acc = fmaf(x_dst[n * 80 + u], w0s[u * 32 + j], acc);
        res = acc * RSQRT32_V;
    } else {
        const int w = (j - 32) / 3;
        const int m = (j - 32) - 3 * w;
        float acc = 0.f;
#pragma unroll
        for (int u = 0; u < 16; u++)
            acc = fmaf(x_dst[n * 80 + 32 + u * 3 + m], w1s[u * 16 + w], acc);
        res = acc * 0.25f;
    }
    const int idx = n * 80 + j;
    out[idx] = fmaf(g_sums[idx], cs[local], res);

    // restore zeros for next replay
    g_sums[idx] = 0.0f;
    if (j == 0) g_cnt[n] = 0.0f;
}

// ---------------------------------------------------------------------------
extern "C" void kernel_launch(void* const* d_in, const int* in_sizes, int n_in,
                              void* d_out, int out_size)
{
    const int*   dst       = (const int*)  d_in[0];
    const float* x_src     = (const float*)d_in[1];
    const float* x_dst     = (const float*)d_in[2];
    const float* sh        = (const float*)d_in[3];
    const float* edge_attr = (const float*)d_in[4];
    const float* w1        = (const float*)d_in[5];
    const float* b1        = (const float*)d_in[6];
    const float* w2        = (const float*)d_in[7];
    const float* b2        = (const float*)d_in[8];
    const float* rw0       = (const float*)d_in[9];
    const float* rw1       = (const float*)d_in[10];
    float* out = (float*)d_out;

    const int E       = in_sizes[0];
    const int n_nodes = in_sizes[2] / OUT_DIM;

    cudaFuncSetAttribute(edge_kernel,
                         cudaFuncAttributeMaxDynamicSharedMemorySize,
                         SMEM_BYTES);

    convert_w2<<<289, 256>>>(w2, w1);
    edge_kernel<<<(E + 63) / 64, 128, SMEM_BYTES>>>(
        E, dst, x_src, sh, edge_attr, b1, b2);
    final_kernel<<<(n_nodes + 3) / 4, 320>>>(
        n_nodes, x_dst, rw0, rw1, out);
}